// round 12
// baseline (speedup 1.0000x reference)
#include <cuda_runtime.h>
#include <math.h>

#define NN   50000
#define EE   300000
#define TOTE (EE + NN)
#define GG   64
#define NB_SCAN 196   // ceil(NN/256)

typedef unsigned long long u64;

// ---------------- scratch (device globals; no allocation allowed) ----------
__device__ float4 g_xw4[NN * 64];   // x @ W   [N, 256] viewed as [N, 64] float4
__device__ float  g_as[NN * 2];
__device__ float  g_ad[NN * 2];
__device__ int    g_deg[NN];
__device__ int    g_off[NN];
__device__ int    g_woff[NN];
__device__ int    g_srcs[TOTE];
__device__ float  g_z[NN * 3];
__device__ int    g_bsum[256];

// ---------------- packed f32x2 helpers ---------------------------------------
__device__ __forceinline__ void fma2(u64& d, u64 a, u64 b) {
    asm("fma.rn.f32x2 %0, %1, %2, %0;" : "+l"(d) : "l"(a), "l"(b));
}
__device__ __forceinline__ u64 bcast2(float x) {
    u64 r;
    asm("mov.b64 %0, {%1, %1};" : "=l"(r) : "f"(x));
    return r;
}
__device__ __forceinline__ u64 pk2(float lo, float hi) {
    u64 r;
    asm("mov.b64 %0, {%1, %2};" : "=l"(r) : "f"(lo), "f"(hi));
    return r;
}
__device__ __forceinline__ void unpack2(u64 v, float& lo, float& hi) {
    asm("mov.b64 {%0, %1}, %2;" : "=f"(lo), "=f"(hi) : "l"(v));
}

// ---------------- kernels ----------------------------------------------------
__global__ void k_init() {
    int i = blockIdx.x * blockDim.x + threadIdx.x;
    if (i < NN) g_deg[i] = 0;
}

// degree histogram of targets
__global__ void k_deg(const int* __restrict__ ei) {
    int e = blockIdx.x * blockDim.x + threadIdx.x;
    if (e >= TOTE) return;
    int t = (e < EE) ? ei[EE + e] : (e - EE);
    if ((unsigned)t < NN) atomicAdd(&g_deg[t], 1);
}

// scan stage 1: per-block sums
__global__ void k_scan1() {
    __shared__ int sp[256];
    int t = threadIdx.x;
    int i = blockIdx.x * 256 + t;
    sp[t] = (i < NN) ? g_deg[i] : 0;
    __syncthreads();
    for (int off = 128; off; off >>= 1) {
        if (t < off) sp[t] += sp[t + off];
        __syncthreads();
    }
    if (t == 0) g_bsum[blockIdx.x] = sp[0];
}

// Tiled GEMM, f32x2 FMA. Block = 32 nodes x 256 cols, 256 threads.
// Thread = 8 nodes x 4 cols -> 16 u64 accumulators (~60 regs, 4 blocks/SM).
// Warp = one head's 128 cols of one 8-node group. Fused a_s/a_d epilogue.
__global__ __launch_bounds__(256) void k_gemm(const float* __restrict__ x,
                                              const float* __restrict__ W,
                                              const float* __restrict__ att_s,
                                              const float* __restrict__ att_d) {
    extern __shared__ float sm[];
    float* xs = sm;                 // [128][36], xs[k*36 + node], 18432 B
    float* ws = sm + 128 * 36;      // [32][256], 32768 B

    int tid = threadIdx.x;
    int tx = tid & 63;              // col group: float4 index 0..63
    int ty = tid >> 6;              // node group 0..3: nodes ty*8 .. +7
    int n0 = blockIdx.x * 32;

    // load x tile transposed (zero-pad past NN): 32 nodes x 128 feats
#pragma unroll
    for (int r = 0; r < 4; r++) {
        int lin4 = r * 256 + tid;          // float4 index in 32x32
        int node = lin4 >> 5;
        int k = (lin4 & 31) * 4;
        float4 v = make_float4(0.f, 0.f, 0.f, 0.f);
        if (n0 + node < NN) v = ((const float4*)x)[(size_t)(n0 + node) * 32 + (lin4 & 31)];
        xs[(k + 0) * 36 + node] = v.x;
        xs[(k + 1) * 36 + node] = v.y;
        xs[(k + 2) * 36 + node] = v.z;
        xs[(k + 3) * 36 + node] = v.w;
    }

    u64 acc2[8][2];
#pragma unroll
    for (int i = 0; i < 8; i++) { acc2[i][0] = 0ull; acc2[i][1] = 0ull; }

    for (int kc = 0; kc < 4; kc++) {
        __syncthreads();
#pragma unroll
        for (int r = 0; r < 8; r++) {
            int lin4 = r * 256 + tid;
            ((float4*)ws)[lin4] = ((const float4*)W)[kc * 2048 + lin4];
        }
        __syncthreads();
#pragma unroll 4
        for (int k = 0; k < 32; k++) {
            const float* xr = &xs[(kc * 32 + k) * 36 + ty * 8];
            float4 a0 = *(const float4*)(xr);
            float4 a1 = *(const float4*)(xr + 4);
            float4 w = *(const float4*)&ws[k * 256 + tx * 4];   // conflict-free
            u64 w0 = pk2(w.x, w.y), w1 = pk2(w.z, w.w);
            float xv[8] = {a0.x, a0.y, a0.z, a0.w, a1.x, a1.y, a1.z, a1.w};
#pragma unroll
            for (int i = 0; i < 8; i++) {
                u64 xp = bcast2(xv[i]);
                fma2(acc2[i][0], xp, w0);
                fma2(acc2[i][1], xp, w1);
            }
        }
    }

    // epilogue: store xw + fused a_s/a_d. Warp covers one head (tx>>5) fully.
    int h = tx >> 5;
    float4 s4 = ((const float4*)att_s)[tx];
    float4 d4 = ((const float4*)att_d)[tx];
#pragma unroll
    for (int i = 0; i < 8; i++) {
        float a0, a1, a2, a3;
        unpack2(acc2[i][0], a0, a1);
        unpack2(acc2[i][1], a2, a3);
        int node = n0 + ty * 8 + i;
        float sp = a0 * s4.x + a1 * s4.y + a2 * s4.z + a3 * s4.w;
        float dp = a0 * d4.x + a1 * d4.y + a2 * d4.z + a3 * d4.w;
#pragma unroll
        for (int off = 16; off; off >>= 1) {
            sp += __shfl_xor_sync(0xffffffffu, sp, off);
            dp += __shfl_xor_sync(0xffffffffu, dp, off);
        }
        if (node < NN) {
            g_xw4[(size_t)node * 64 + tx] = make_float4(a0, a1, a2, a3);
            if ((tx & 31) == 0) {
                g_as[2 * node + h] = sp;
                g_ad[2 * node + h] = dp;
            }
        }
    }
}

// scan stage 2+3 fused
__global__ void k_scanB() {
    __shared__ int sb[256];
    __shared__ int sp[256];
    int t = threadIdx.x;
    int b = blockIdx.x;

    sb[t] = (t < NB_SCAN) ? g_bsum[t] : 0;
    __syncthreads();
    for (int off = 1; off < 256; off <<= 1) {
        int u = (t >= off) ? sb[t - off] : 0;
        __syncthreads();
        sb[t] += u;
        __syncthreads();
    }
    int base = (b == 0) ? 0 : sb[b - 1];

    int i = b * 256 + t;
    int v = (i < NN) ? g_deg[i] : 0;
    sp[t] = v;
    __syncthreads();
    for (int off = 1; off < 256; off <<= 1) {
        int u = (t >= off) ? sp[t - off] : 0;
        __syncthreads();
        sp[t] += u;
        __syncthreads();
    }
    int excl = sp[t] - v + base;
    if (i < NN) { g_off[i] = excl; g_woff[i] = excl; }
}

// scatter: sources grouped by target
__global__ void k_scatter(const int* __restrict__ ei) {
    int e = blockIdx.x * blockDim.x + threadIdx.x;
    if (e >= TOTE) return;
    int s, t;
    if (e < EE) { s = ei[e]; t = ei[EE + e]; }
    else        { s = t = e - EE; }
    if ((unsigned)t >= NN || (unsigned)s >= NN) return;
    int pos = atomicAdd(&g_woff[t], 1);
    if ((unsigned)pos < TOTE) g_srcs[pos] = s;
}

// fused node kernel, 2 warps per node (one per head). lane owns 4 cols.
__global__ void k_node(const float* __restrict__ bias, const float* __restrict__ fcw,
                       const float* __restrict__ fcb) {
    __shared__ float zpart[8][3];
    int tid  = threadIdx.x;
    int lane = tid & 31;
    int winb = tid >> 5;                         // warp in block (0..7)
    int gw   = blockIdx.x * 8 + winb;            // global warp
    int n    = gw >> 1;                          // node
    int h    = gw & 1;                           // head

    int off = g_off[n], deg = g_deg[n];
    float adh = g_ad[2 * n + h];

    // pass A: segment max for this head (leaky is monotone)
    float mas = -INFINITY;
    for (int i = lane; i < deg; i += 32)
        mas = fmaxf(mas, g_as[2 * g_srcs[off + i] + h]);
#pragma unroll
    for (int o = 16; o; o >>= 1)
        mas = fmaxf(mas, __shfl_xor_sync(0xffffffffu, mas, o));
    float m = mas + adh; m = m > 0.f ? m : 0.2f * m;

    float4 acc = make_float4(0.f, 0.f, 0.f, 0.f);
    float den = 0.f;

    for (int i0 = 0; i0 < deg; i0 += 32) {
        int cnt = min(32, deg - i0);
        int s = 0; float ex = 0.f;
        if (lane < cnt) {
            s = g_srcs[off + i0 + lane];
            float l = g_as[2 * s + h] + adh; l = l > 0.f ? l : 0.2f * l;
            ex = expf(l - m);
        }
        den += ex;

        // pipelined gather: load edge j+1 while accumulating edge j
        int s0i = __shfl_sync(0xffffffffu, s, 0);
        float4 v = g_xw4[(size_t)s0i * 64 + h * 32 + lane];
        for (int j = 0; j < cnt; j++) {
            float4 nv;
            if (j + 1 < cnt) {
                int sn = __shfl_sync(0xffffffffu, s, j + 1);
                nv = g_xw4[(size_t)sn * 64 + h * 32 + lane];
            }
            float e = __shfl_sync(0xffffffffu, ex, j);
            acc.x += e * v.x; acc.y += e * v.y;
            acc.z += e * v.z; acc.w += e * v.w;
            if (j + 1 < cnt) v = nv;
        }
    }
#pragma unroll
    for (int o = 16; o; o >>= 1)
        den += __shfl_xor_sync(0xffffffffu, den, o);
    float inv = 1.f / den;

    // FC partial over this head's 128 cols (lane owns 4)
    int cb = h * 128 + lane * 4;
    float4 b4 = *(const float4*)&bias[cb];
    float vv[4] = {acc.x * inv + b4.x, acc.y * inv + b4.y,
                   acc.z * inv + b4.z, acc.w * inv + b4.w};
    float z0 = 0.f, z1 = 0.f, z2 = 0.f;
#pragma unroll
    for (int mth = 0; mth < 4; mth++) {
        float val = vv[mth] > 0.f ? vv[mth] : 0.f;
        int k = cb + mth;
        z0 += val * fcw[k * 3 + 0];
        z1 += val * fcw[k * 3 + 1];
        z2 += val * fcw[k * 3 + 2];
    }
#pragma unroll
    for (int o = 16; o; o >>= 1) {
        z0 += __shfl_xor_sync(0xffffffffu, z0, o);
        z1 += __shfl_xor_sync(0xffffffffu, z1, o);
        z2 += __shfl_xor_sync(0xffffffffu, z2, o);
    }
    if (lane == 0) { zpart[winb][0] = z0; zpart[winb][1] = z1; zpart[winb][2] = z2; }
    __syncthreads();
    if (h == 0 && lane == 0) {
        float p0 = zpart[winb][0] + zpart[winb + 1][0] + fcb[0];
        float p1 = zpart[winb][1] + zpart[winb + 1][1] + fcb[1];
        float p2 = zpart[winb][2] + zpart[winb + 1][2] + fcb[2];
        float mx = fmaxf(p0, fmaxf(p1, p2));
        float ls = mx + logf(expf(p0 - mx) + expf(p1 - mx) + expf(p2 - mx));
        g_z[n * 3 + 0] = p0 - ls;
        g_z[n * 3 + 1] = p1 - ls;
        g_z[n * 3 + 2] = p2 - ls;
    }
}

// deterministic pool: batch sorted -> contiguous node range per graph.
__global__ void k_pool(const int* __restrict__ batch, const float* __restrict__ a,
                       float* __restrict__ out) {
    __shared__ float sz[3][256];
    int g = blockIdx.x;
    int t = threadIdx.x;
    int lo = 0, hi = NN;
    while (lo < hi) { int mid = (lo + hi) >> 1; if (batch[mid] < g) lo = mid + 1; else hi = mid; }
    int s0 = lo;
    hi = NN;
    while (lo < hi) { int mid = (lo + hi) >> 1; if (batch[mid] < g + 1) lo = mid + 1; else hi = mid; }
    int e0 = lo;

    float z0 = 0.f, z1 = 0.f, z2 = 0.f;
    for (int n = s0 + t; n < e0; n += 256) {
        z0 += g_z[n * 3 + 0];
        z1 += g_z[n * 3 + 1];
        z2 += g_z[n * 3 + 2];
    }
    sz[0][t] = z0; sz[1][t] = z1; sz[2][t] = z2;
    __syncthreads();
    for (int off = 128; off; off >>= 1) {
        if (t < off) {
            sz[0][t] += sz[0][t + off];
            sz[1][t] += sz[1][t + off];
            sz[2][t] += sz[2][t + off];
        }
        __syncthreads();
    }
    if (t == 0) {
        float sc = *a;
        float p0 = sc * sz[0][0], p1 = sc * sz[1][0], p2 = sc * sz[2][0];
        float mx = fmaxf(p0, fmaxf(p1, p2));
        float ls = mx + logf(expf(p0 - mx) + expf(p1 - mx) + expf(p2 - mx));
        out[g * 3 + 0] = p0 - ls;
        out[g * 3 + 1] = p1 - ls;
        out[g * 3 + 2] = p2 - ls;
    }
}

// ---------------- launch -----------------------------------------------------
extern "C" void kernel_launch(void* const* d_in, const int* in_sizes, int n_in,
                              void* d_out, int out_size) {
    const float* x     = (const float*)d_in[0];
    const int*   ei    = (const int*)d_in[1];
    const int*   batch = (const int*)d_in[2];
    const float* W     = (const float*)d_in[3];
    const float* att_s = (const float*)d_in[4];
    const float* att_d = (const float*)d_in[5];
    const float* bias  = (const float*)d_in[6];
    const float* fcw   = (const float*)d_in[7];
    const float* fcb   = (const float*)d_in[8];
    const float* a     = (const float*)d_in[9];
    float* out = (float*)d_out;

    const int SMEM = (128 * 36 + 32 * 256) * 4;   // 51200 B

    static cudaStream_t s2 = 0;
    static cudaEvent_t evA = 0, evB = 0;
    if (s2 == 0) {
        cudaStreamCreateWithFlags(&s2, cudaStreamNonBlocking);
        cudaEventCreateWithFlags(&evA, cudaEventDisableTiming);
        cudaEventCreateWithFlags(&evB, cudaEventDisableTiming);
        cudaFuncSetAttribute(k_gemm, cudaFuncAttributeMaxDynamicSharedMemorySize, SMEM);
    }

    // main stream: init -> gemm ; side stream: CSR chain (independent of gemm)
    k_init   <<<(NN + 255) / 256, 256>>>();
    cudaEventRecord(evA, 0);
    cudaStreamWaitEvent(s2, evA, 0);
    k_deg    <<<(TOTE + 255) / 256, 256, 0, s2>>>(ei);
    k_scan1  <<<NB_SCAN, 256, 0, s2>>>();
    k_gemm   <<<(NN + 31) / 32, 256, SMEM>>>(x, W, att_s, att_d);   // 4th submission: profiled
    k_scanB  <<<NB_SCAN, 256, 0, s2>>>();
    k_scatter<<<(TOTE + 255) / 256, 256, 0, s2>>>(ei);
    cudaEventRecord(evB, s2);
    cudaStreamWaitEvent(0, evB, 0);
    k_node   <<<(NN * 2) / 8, 256>>>(bias, fcw, fcb);
    k_pool   <<<GG, 256>>>(batch, a, out);
}

// round 13
// speedup vs baseline: 1.0022x; 1.0022x over previous
#include <cuda_runtime.h>
#include <math.h>

#define NN   50000
#define EE   300000
#define TOTE (EE + NN)
#define GG   64
#define NB_SCAN 196   // ceil(NN/256)

typedef unsigned long long u64;

// ---------------- scratch (device globals; no allocation allowed) ----------
__device__ float4 g_xw4[NN * 64];   // x @ W   [N, 256] viewed as [N, 64] float4
__device__ float  g_as[NN * 2];
__device__ float  g_ad[NN * 2];
__device__ int    g_deg[NN];
__device__ int    g_off[NN];
__device__ int    g_woff[NN];
__device__ int    g_srcs[TOTE];
__device__ float  g_z[NN * 3];
__device__ int    g_bsum[256];

// ---------------- packed f32x2 helpers ---------------------------------------
__device__ __forceinline__ void fma2(u64& d, u64 a, u64 b) {
    asm("fma.rn.f32x2 %0, %1, %2, %0;" : "+l"(d) : "l"(a), "l"(b));
}
__device__ __forceinline__ u64 bcast2(float x) {
    u64 r;
    asm("mov.b64 %0, {%1, %1};" : "=l"(r) : "f"(x));
    return r;
}
__device__ __forceinline__ void unpack2(u64 v, float& lo, float& hi) {
    asm("mov.b64 {%0, %1}, %2;" : "=f"(lo), "=f"(hi) : "l"(v));
}

// ---------------- kernels ----------------------------------------------------
__global__ void k_init() {
    int i = blockIdx.x * blockDim.x + threadIdx.x;
    if (i < NN) g_deg[i] = 0;
}

// degree histogram of targets
__global__ void k_deg(const int* __restrict__ ei) {
    int e = blockIdx.x * blockDim.x + threadIdx.x;
    if (e >= TOTE) return;
    int t = (e < EE) ? ei[EE + e] : (e - EE);
    if ((unsigned)t < NN) atomicAdd(&g_deg[t], 1);
}

// scan stage 1: per-block sums
__global__ void k_scan1() {
    __shared__ int sp[256];
    int t = threadIdx.x;
    int i = blockIdx.x * 256 + t;
    sp[t] = (i < NN) ? g_deg[i] : 0;
    __syncthreads();
    for (int off = 128; off; off >>= 1) {
        if (t < off) sp[t] += sp[t + off];
        __syncthreads();
    }
    if (t == 0) g_bsum[blockIdx.x] = sp[0];
}

// Tiled GEMM, f32x2 FMA with node-pair packing; W streamed from global (L2).
// Block = 64 nodes x 256 cols, 8 warps; warp = 8 nodes (4 node-pairs),
// lane cols = {tx*4..+3} (head0) and {128+tx*4..+3} (head1).
// xs[k][node] layout: a u64 read packs two adjacent nodes for f32x2 directly.
__global__ __launch_bounds__(256) void k_gemm(const float* __restrict__ x,
                                              const float* __restrict__ W,
                                              const float* __restrict__ att_s,
                                              const float* __restrict__ att_d) {
    __shared__ __align__(16) float xs[128 * 68];   // [k][node], 34816 B

    int tid = threadIdx.x;
    int tx = tid & 31;
    int ty = tid >> 5;              // warp id: nodes ty*8 .. +7
    int n0 = blockIdx.x * 64;

    // load x tile transposed (zero-pad past NN)
#pragma unroll
    for (int r = 0; r < 8; r++) {
        int lin4 = r * 256 + tid;
        int node = lin4 >> 5;
        int k = (lin4 & 31) * 4;
        float4 v = make_float4(0.f, 0.f, 0.f, 0.f);
        if (n0 + node < NN) v = ((const float4*)x)[(size_t)(n0 + node) * 32 + (lin4 & 31)];
        xs[(k + 0) * 68 + node] = v.x;
        xs[(k + 1) * 68 + node] = v.y;
        xs[(k + 2) * 68 + node] = v.z;
        xs[(k + 3) * 68 + node] = v.w;
    }
    __syncthreads();

    // acc[p][c]: node-pair p (nodes ty*8+2p lo, +2p+1 hi), col-slot c
    // (c 0..3 -> cols tx*4+c ; c 4..7 -> cols 128+tx*4+(c-4))
    u64 acc[4][8];
#pragma unroll
    for (int p = 0; p < 4; p++)
#pragma unroll
        for (int c = 0; c < 8; c++) acc[p][c] = 0ull;

    const float4* Wp = (const float4*)W;   // W[k][256] -> row k at k*64 float4s
#pragma unroll 4
    for (int k = 0; k < 128; k++) {
        const u64* xp = (const u64*)&xs[k * 68 + ty * 8];   // 4 node-pairs (broadcast)
        u64 x0 = xp[0], x1 = xp[1], x2 = xp[2], x3 = xp[3];
        float4 wa = Wp[k * 64 + tx];        // cols tx*4..+3      (coalesced L2)
        float4 wb = Wp[k * 64 + 32 + tx];   // cols 128+tx*4..+3
        u64 w0 = bcast2(wa.x), w1 = bcast2(wa.y), w2 = bcast2(wa.z), w3 = bcast2(wa.w);
        u64 w4 = bcast2(wb.x), w5 = bcast2(wb.y), w6 = bcast2(wb.z), w7 = bcast2(wb.w);
        u64 xv[4] = {x0, x1, x2, x3};
#pragma unroll
        for (int p = 0; p < 4; p++) {
            fma2(acc[p][0], xv[p], w0);
            fma2(acc[p][1], xv[p], w1);
            fma2(acc[p][2], xv[p], w2);
            fma2(acc[p][3], xv[p], w3);
            fma2(acc[p][4], xv[p], w4);
            fma2(acc[p][5], xv[p], w5);
            fma2(acc[p][6], xv[p], w6);
            fma2(acc[p][7], xv[p], w7);
        }
    }

    // epilogue: store xw + fused a_s/a_d
    float4 s0 = *(const float4*)&att_s[tx * 4];
    float4 s1 = *(const float4*)&att_s[128 + tx * 4];
    float4 d0 = *(const float4*)&att_d[tx * 4];
    float4 d1 = *(const float4*)&att_d[128 + tx * 4];
#pragma unroll
    for (int p = 0; p < 4; p++) {
#pragma unroll
        for (int b = 0; b < 2; b++) {
            float a[8];
#pragma unroll
            for (int c = 0; c < 8; c++) {
                float lo, hi;
                unpack2(acc[p][c], lo, hi);
                a[c] = b ? hi : lo;
            }
            int node = n0 + ty * 8 + 2 * p + b;
            float sp0 = a[0] * s0.x + a[1] * s0.y + a[2] * s0.z + a[3] * s0.w;
            float sp1 = a[4] * s1.x + a[5] * s1.y + a[6] * s1.z + a[7] * s1.w;
            float dp0 = a[0] * d0.x + a[1] * d0.y + a[2] * d0.z + a[3] * d0.w;
            float dp1 = a[4] * d1.x + a[5] * d1.y + a[6] * d1.z + a[7] * d1.w;
#pragma unroll
            for (int off = 16; off; off >>= 1) {
                sp0 += __shfl_xor_sync(0xffffffffu, sp0, off);
                sp1 += __shfl_xor_sync(0xffffffffu, sp1, off);
                dp0 += __shfl_xor_sync(0xffffffffu, dp0, off);
                dp1 += __shfl_xor_sync(0xffffffffu, dp1, off);
            }
            if (node < NN) {
                g_xw4[(size_t)node * 64 + tx]      = make_float4(a[0], a[1], a[2], a[3]);
                g_xw4[(size_t)node * 64 + 32 + tx] = make_float4(a[4], a[5], a[6], a[7]);
                if (tx == 0) {
                    g_as[2 * node]     = sp0;
                    g_as[2 * node + 1] = sp1;
                    g_ad[2 * node]     = dp0;
                    g_ad[2 * node + 1] = dp1;
                }
            }
        }
    }
}

// scan stage 2+3 fused
__global__ void k_scanB() {
    __shared__ int sb[256];
    __shared__ int sp[256];
    int t = threadIdx.x;
    int b = blockIdx.x;

    sb[t] = (t < NB_SCAN) ? g_bsum[t] : 0;
    __syncthreads();
    for (int off = 1; off < 256; off <<= 1) {
        int u = (t >= off) ? sb[t - off] : 0;
        __syncthreads();
        sb[t] += u;
        __syncthreads();
    }
    int base = (b == 0) ? 0 : sb[b - 1];

    int i = b * 256 + t;
    int v = (i < NN) ? g_deg[i] : 0;
    sp[t] = v;
    __syncthreads();
    for (int off = 1; off < 256; off <<= 1) {
        int u = (t >= off) ? sp[t - off] : 0;
        __syncthreads();
        sp[t] += u;
        __syncthreads();
    }
    int excl = sp[t] - v + base;
    if (i < NN) { g_off[i] = excl; g_woff[i] = excl; }
}

// scatter: sources grouped by target
__global__ void k_scatter(const int* __restrict__ ei) {
    int e = blockIdx.x * blockDim.x + threadIdx.x;
    if (e >= TOTE) return;
    int s, t;
    if (e < EE) { s = ei[e]; t = ei[EE + e]; }
    else        { s = t = e - EE; }
    if ((unsigned)t >= NN || (unsigned)s >= NN) return;
    int pos = atomicAdd(&g_woff[t], 1);
    if ((unsigned)pos < TOTE) g_srcs[pos] = s;
}

// fused node kernel, 2 warps per node (one per head). lane owns 4 cols.
// gather loop unrolled x4: four independent loads in flight (MLP=4).
__global__ void k_node(const float* __restrict__ bias, const float* __restrict__ fcw,
                       const float* __restrict__ fcb) {
    __shared__ float zpart[8][3];
    int tid  = threadIdx.x;
    int lane = tid & 31;
    int winb = tid >> 5;                         // warp in block (0..7)
    int gw   = blockIdx.x * 8 + winb;            // global warp
    int n    = gw >> 1;                          // node
    int h    = gw & 1;                           // head

    int off = g_off[n], deg = g_deg[n];
    float adh = g_ad[2 * n + h];

    // pass A: segment max for this head (leaky is monotone)
    float mas = -INFINITY;
    for (int i = lane; i < deg; i += 32)
        mas = fmaxf(mas, g_as[2 * g_srcs[off + i] + h]);
#pragma unroll
    for (int o = 16; o; o >>= 1)
        mas = fmaxf(mas, __shfl_xor_sync(0xffffffffu, mas, o));
    float m = mas + adh; m = m > 0.f ? m : 0.2f * m;

    float4 acc = make_float4(0.f, 0.f, 0.f, 0.f);
    float den = 0.f;
    const float4* xwb = g_xw4 + h * 32 + lane;

    for (int i0 = 0; i0 < deg; i0 += 32) {
        int cnt = min(32, deg - i0);
        int s = 0; float ex = 0.f;
        if (lane < cnt) {
            s = g_srcs[off + i0 + lane];
            float l = g_as[2 * s + h] + adh; l = l > 0.f ? l : 0.2f * l;
            ex = expf(l - m);
        }
        den += ex;

        int j = 0;
        for (; j + 4 <= cnt; j += 4) {
            int s0 = __shfl_sync(0xffffffffu, s, j);
            int s1 = __shfl_sync(0xffffffffu, s, j + 1);
            int s2 = __shfl_sync(0xffffffffu, s, j + 2);
            int s3 = __shfl_sync(0xffffffffu, s, j + 3);
            float4 v0 = xwb[(size_t)s0 * 64];
            float4 v1 = xwb[(size_t)s1 * 64];
            float4 v2 = xwb[(size_t)s2 * 64];
            float4 v3 = xwb[(size_t)s3 * 64];
            float e0 = __shfl_sync(0xffffffffu, ex, j);
            float e1 = __shfl_sync(0xffffffffu, ex, j + 1);
            float e2 = __shfl_sync(0xffffffffu, ex, j + 2);
            float e3 = __shfl_sync(0xffffffffu, ex, j + 3);
            acc.x += e0 * v0.x; acc.y += e0 * v0.y; acc.z += e0 * v0.z; acc.w += e0 * v0.w;
            acc.x += e1 * v1.x; acc.y += e1 * v1.y; acc.z += e1 * v1.z; acc.w += e1 * v1.w;
            acc.x += e2 * v2.x; acc.y += e2 * v2.y; acc.z += e2 * v2.z; acc.w += e2 * v2.w;
            acc.x += e3 * v3.x; acc.y += e3 * v3.y; acc.z += e3 * v3.z; acc.w += e3 * v3.w;
        }
        for (; j < cnt; j++) {
            int sj = __shfl_sync(0xffffffffu, s, j);
            float4 v = xwb[(size_t)sj * 64];
            float e = __shfl_sync(0xffffffffu, ex, j);
            acc.x += e * v.x; acc.y += e * v.y; acc.z += e * v.z; acc.w += e * v.w;
        }
    }
#pragma unroll
    for (int o = 16; o; o >>= 1)
        den += __shfl_xor_sync(0xffffffffu, den, o);
    float inv = 1.f / den;

    // FC partial over this head's 128 cols (lane owns 4)
    int cb = h * 128 + lane * 4;
    float4 b4 = *(const float4*)&bias[cb];
    float vv[4] = {acc.x * inv + b4.x, acc.y * inv + b4.y,
                   acc.z * inv + b4.z, acc.w * inv + b4.w};
    float z0 = 0.f, z1 = 0.f, z2 = 0.f;
#pragma unroll
    for (int mth = 0; mth < 4; mth++) {
        float val = vv[mth] > 0.f ? vv[mth] : 0.f;
        int k = cb + mth;
        z0 += val * fcw[k * 3 + 0];
        z1 += val * fcw[k * 3 + 1];
        z2 += val * fcw[k * 3 + 2];
    }
#pragma unroll
    for (int o = 16; o; o >>= 1) {
        z0 += __shfl_xor_sync(0xffffffffu, z0, o);
        z1 += __shfl_xor_sync(0xffffffffu, z1, o);
        z2 += __shfl_xor_sync(0xffffffffu, z2, o);
    }
    if (lane == 0) { zpart[winb][0] = z0; zpart[winb][1] = z1; zpart[winb][2] = z2; }
    __syncthreads();
    if (h == 0 && lane == 0) {
        float p0 = zpart[winb][0] + zpart[winb + 1][0] + fcb[0];
        float p1 = zpart[winb][1] + zpart[winb + 1][1] + fcb[1];
        float p2 = zpart[winb][2] + zpart[winb + 1][2] + fcb[2];
        float mx = fmaxf(p0, fmaxf(p1, p2));
        float ls = mx + logf(expf(p0 - mx) + expf(p1 - mx) + expf(p2 - mx));
        g_z[n * 3 + 0] = p0 - ls;
        g_z[n * 3 + 1] = p1 - ls;
        g_z[n * 3 + 2] = p2 - ls;
    }
}

// deterministic pool: batch sorted -> contiguous node range per graph.
__global__ void k_pool(const int* __restrict__ batch, const float* __restrict__ a,
                       float* __restrict__ out) {
    __shared__ float sz[3][256];
    int g = blockIdx.x;
    int t = threadIdx.x;
    int lo = 0, hi = NN;
    while (lo < hi) { int mid = (lo + hi) >> 1; if (batch[mid] < g) lo = mid + 1; else hi = mid; }
    int s0 = lo;
    hi = NN;
    while (lo < hi) { int mid = (lo + hi) >> 1; if (batch[mid] < g + 1) lo = mid + 1; else hi = mid; }
    int e0 = lo;

    float z0 = 0.f, z1 = 0.f, z2 = 0.f;
    for (int n = s0 + t; n < e0; n += 256) {
        z0 += g_z[n * 3 + 0];
        z1 += g_z[n * 3 + 1];
        z2 += g_z[n * 3 + 2];
    }
    sz[0][t] = z0; sz[1][t] = z1; sz[2][t] = z2;
    __syncthreads();
    for (int off = 128; off; off >>= 1) {
        if (t < off) {
            sz[0][t] += sz[0][t + off];
            sz[1][t] += sz[1][t + off];
            sz[2][t] += sz[2][t + off];
        }
        __syncthreads();
    }
    if (t == 0) {
        float sc = *a;
        float p0 = sc * sz[0][0], p1 = sc * sz[1][0], p2 = sc * sz[2][0];
        float mx = fmaxf(p0, fmaxf(p1, p2));
        float ls = mx + logf(expf(p0 - mx) + expf(p1 - mx) + expf(p2 - mx));
        out[g * 3 + 0] = p0 - ls;
        out[g * 3 + 1] = p1 - ls;
        out[g * 3 + 2] = p2 - ls;
    }
}

// ---------------- launch -----------------------------------------------------
extern "C" void kernel_launch(void* const* d_in, const int* in_sizes, int n_in,
                              void* d_out, int out_size) {
    const float* x     = (const float*)d_in[0];
    const int*   ei    = (const int*)d_in[1];
    const int*   batch = (const int*)d_in[2];
    const float* W     = (const float*)d_in[3];
    const float* att_s = (const float*)d_in[4];
    const float* att_d = (const float*)d_in[5];
    const float* bias  = (const float*)d_in[6];
    const float* fcw   = (const float*)d_in[7];
    const float* fcb   = (const float*)d_in[8];
    const float* a     = (const float*)d_in[9];
    float* out = (float*)d_out;

    static cudaStream_t s2 = 0;
    static cudaEvent_t evA = 0, evB = 0;
    if (s2 == 0) {
        cudaStreamCreateWithFlags(&s2, cudaStreamNonBlocking);
        cudaEventCreateWithFlags(&evA, cudaEventDisableTiming);
        cudaEventCreateWithFlags(&evB, cudaEventDisableTiming);
    }

    // main stream: init -> gemm ; side stream: CSR chain (independent of gemm)
    k_init   <<<(NN + 255) / 256, 256>>>();
    cudaEventRecord(evA, 0);
    cudaStreamWaitEvent(s2, evA, 0);
    k_deg    <<<(TOTE + 255) / 256, 256, 0, s2>>>(ei);
    k_scan1  <<<NB_SCAN, 256, 0, s2>>>();
    k_gemm   <<<(NN + 63) / 64, 256>>>(x, W, att_s, att_d);   // 4th submission: profiled
    k_scanB  <<<NB_SCAN, 256, 0, s2>>>();
    k_scatter<<<(TOTE + 255) / 256, 256, 0, s2>>>(ei);
    cudaEventRecord(evB, s2);
    cudaStreamWaitEvent(0, evB, 0);
    k_node   <<<(NN * 2) / 8, 256>>>(bias, fcw, fcb);
    k_pool   <<<GG, 256>>>(batch, a, out);
}

// round 14
// speedup vs baseline: 1.2160x; 1.2133x over previous
#include <cuda_runtime.h>
#include <cuda_bf16.h>
#include <math.h>

#define NN   50000
#define EE   300000
#define TOTE (EE + NN)
#define GG   64
#define NB_SCAN 196   // ceil(NN/256)

typedef unsigned int u32;

// ---------------- scratch (device globals; no allocation allowed) ----------
__device__ float4 g_xw4[NN * 64];   // x @ W   [N, 256] viewed as [N, 64] float4
__device__ float  g_as[NN * 2];
__device__ float  g_ad[NN * 2];
__device__ int    g_deg[NN];
__device__ int    g_off[NN];
__device__ int    g_woff[NN];
__device__ int    g_srcs[TOTE];
__device__ float  g_z[NN * 3];
__device__ int    g_bsum[256];
__device__ __nv_bfloat16 g_wh[8 * 256 * 16];  // W^T hi, kstep-blocked [ks][col][kl]
__device__ __nv_bfloat16 g_wl[8 * 256 * 16];  // W^T lo

// ---------------- helpers -----------------------------------------------------
__device__ __forceinline__ u32 pack_hi(float a, float b, float& la, float& lb) {
    __nv_bfloat16 ha = __float2bfloat16(a), hb = __float2bfloat16(b);
    la = a - __bfloat162float(ha);
    lb = b - __bfloat162float(hb);
    return (u32)__bfloat16_as_ushort(ha) | ((u32)__bfloat16_as_ushort(hb) << 16);
}
__device__ __forceinline__ u32 pack_bf(float a, float b) {
    return (u32)__bfloat16_as_ushort(__float2bfloat16(a)) |
           ((u32)__bfloat16_as_ushort(__float2bfloat16(b)) << 16);
}
__device__ __forceinline__ void mma_bf16(float* d, u32 a0, u32 a1, u32 a2, u32 a3,
                                         u32 b0, u32 b1) {
    asm volatile(
        "mma.sync.aligned.m16n8k16.row.col.f32.bf16.bf16.f32 "
        "{%0,%1,%2,%3}, {%4,%5,%6,%7}, {%8,%9}, {%0,%1,%2,%3};"
        : "+f"(d[0]), "+f"(d[1]), "+f"(d[2]), "+f"(d[3])
        : "r"(a0), "r"(a1), "r"(a2), "r"(a3), "r"(b0), "r"(b1));
}

// ---------------- kernels ----------------------------------------------------
__global__ void k_init() {
    int i = blockIdx.x * blockDim.x + threadIdx.x;
    if (i < NN) g_deg[i] = 0;
}

// W prep: bf16 hi/lo split, transposed + kstep-blocked: [ks][col][kl]
__global__ void k_wprep(const float* __restrict__ W) {
    int i = blockIdx.x * 256 + threadIdx.x;
    if (i >= 128 * 256) return;
    int k = i >> 8, col = i & 255;
    float v = W[i];
    __nv_bfloat16 h = __float2bfloat16(v);
    float l = v - __bfloat162float(h);
    int o = (k >> 4) * 4096 + col * 16 + (k & 15);
    g_wh[o] = h;
    g_wl[o] = __float2bfloat16(l);
}

// degree histogram of targets
__global__ void k_deg(const int* __restrict__ ei) {
    int e = blockIdx.x * blockDim.x + threadIdx.x;
    if (e >= TOTE) return;
    int t = (e < EE) ? ei[EE + e] : (e - EE);
    if ((unsigned)t < NN) atomicAdd(&g_deg[t], 1);
}

// scan stage 1: per-block sums
__global__ void k_scan1() {
    __shared__ int sp[256];
    int t = threadIdx.x;
    int i = blockIdx.x * 256 + t;
    sp[t] = (i < NN) ? g_deg[i] : 0;
    __syncthreads();
    for (int off = 128; off; off >>= 1) {
        if (t < off) sp[t] += sp[t + off];
        __syncthreads();
    }
    if (t == 0) g_bsum[blockIdx.x] = sp[0];
}

// Tensor-core GEMM via mma.sync bf16 split precision (hi*hi + hi*lo + lo*hi).
// Block = 64 nodes; warp = 16 nodes x 128 cols (one head -> local a_s/a_d).
// smem: x hi/lo [64 rows][272B pitch], W kstep [256 cols][48B pitch],
// D drain tile [64][260 floats] aliases everything after a sync.
#define XHO 0
#define XLO 17408
#define WHO 34816
#define WLO 47104
#define GSM 66560
__global__ __launch_bounds__(256) void k_gemm(const float* __restrict__ x,
                                              const float* __restrict__ att_s,
                                              const float* __restrict__ att_d) {
    extern __shared__ char smc[];
    int tid  = threadIdx.x;
    int lane = tid & 31;
    int w    = tid >> 5;
    int ng   = w >> 1, cg = w & 1;    // node group 0..3, col group (=head) 0..1
    int g    = lane >> 2, t = lane & 3;
    int n0   = blockIdx.x * 64;

    // x fill: 64 nodes x 128 feats -> bf16 hi/lo, row pitch 272B
#pragma unroll
    for (int r = 0; r < 8; r++) {
        int lin4 = r * 256 + tid;
        int node = lin4 >> 5, kq = lin4 & 31;
        float4 v = make_float4(0.f, 0.f, 0.f, 0.f);
        if (n0 + node < NN) v = ((const float4*)x)[(size_t)(n0 + node) * 32 + kq];
        float lx, ly, lz, lw;
        u32 h01 = pack_hi(v.x, v.y, lx, ly);
        u32 h23 = pack_hi(v.z, v.w, lz, lw);
        u32 l01 = pack_bf(lx, ly), l23 = pack_bf(lz, lw);
        int off = node * 272 + kq * 8;
        *(u32*)(smc + XHO + off)     = h01;
        *(u32*)(smc + XHO + off + 4) = h23;
        *(u32*)(smc + XLO + off)     = l01;
        *(u32*)(smc + XLO + off + 4) = l23;
    }

    float acc[16][4];
#pragma unroll
    for (int ct = 0; ct < 16; ct++)
#pragma unroll
        for (int c = 0; c < 4; c++) acc[ct][c] = 0.f;

    const uint4* gwh = (const uint4*)g_wh;
    const uint4* gwl = (const uint4*)g_wl;
    for (int ks = 0; ks < 8; ks++) {
        // coalesced W kstep load: thread = one col's 16 k (32B hi + 32B lo)
        uint4 h0 = gwh[ks * 512 + tid * 2], h1 = gwh[ks * 512 + tid * 2 + 1];
        uint4 l0 = gwl[ks * 512 + tid * 2], l1 = gwl[ks * 512 + tid * 2 + 1];
        __syncthreads();   // also orders x-fill before first compute
        *(uint4*)(smc + WHO + tid * 48)      = h0;
        *(uint4*)(smc + WHO + tid * 48 + 16) = h1;
        *(uint4*)(smc + WLO + tid * 48)      = l0;
        *(uint4*)(smc + WLO + tid * 48 + 16) = l1;
        __syncthreads();

        // A fragments (rows ng*16+g / +8, k = ks*16 + {2t, 2t+8})
        int ab = XHO + (ng * 16 + g) * 272 + ks * 32 + 4 * t;
        u32 ah0 = *(u32*)(smc + ab),        ah1 = *(u32*)(smc + ab + 2176);
        u32 ah2 = *(u32*)(smc + ab + 16),   ah3 = *(u32*)(smc + ab + 2192);
        int abl = ab + (XLO - XHO);
        u32 al0 = *(u32*)(smc + abl),       al1 = *(u32*)(smc + abl + 2176);
        u32 al2 = *(u32*)(smc + abl + 16),  al3 = *(u32*)(smc + abl + 2192);

        int wb0 = WHO + (cg * 128 + g) * 48 + 4 * t;
#pragma unroll
        for (int ct = 0; ct < 16; ct++) {
            int wb = wb0 + ct * 384;   // 8 cols * 48B
            u32 bh0 = *(u32*)(smc + wb),                 bh1 = *(u32*)(smc + wb + 16);
            u32 bl0 = *(u32*)(smc + wb + (WLO - WHO));
            u32 bl1 = *(u32*)(smc + wb + (WLO - WHO) + 16);
            mma_bf16(acc[ct], ah0, ah1, ah2, ah3, bh0, bh1);
            mma_bf16(acc[ct], ah0, ah1, ah2, ah3, bl0, bl1);
            mma_bf16(acc[ct], al0, al1, al2, al3, bh0, bh1);
        }
    }
    __syncthreads();

    // drain fragments -> smem D tile [64][260 floats]
#pragma unroll
    for (int ct = 0; ct < 16; ct++) {
        int row = ng * 16 + g, col = cg * 128 + ct * 8 + 2 * t;
        *(float2*)(smc + (row * 260 + col) * 4)       = make_float2(acc[ct][0], acc[ct][1]);
        *(float2*)(smc + ((row + 8) * 260 + col) * 4) = make_float2(acc[ct][2], acc[ct][3]);
    }
    __syncthreads();

    // epilogue: coalesced store + fused a_s/a_d (warp = 8 nodes)
    float4 s0 = *(const float4*)&att_s[lane * 4];
    float4 s1 = *(const float4*)&att_s[128 + lane * 4];
    float4 d0 = *(const float4*)&att_d[lane * 4];
    float4 d1 = *(const float4*)&att_d[128 + lane * 4];
#pragma unroll
    for (int i = 0; i < 8; i++) {
        int rowl = w * 8 + i;
        float4 a03 = *(float4*)(smc + (rowl * 260 + lane * 4) * 4);
        float4 a47 = *(float4*)(smc + (rowl * 260 + 128 + lane * 4) * 4);
        int node = n0 + rowl;
        float sp0 = a03.x * s0.x + a03.y * s0.y + a03.z * s0.z + a03.w * s0.w;
        float sp1 = a47.x * s1.x + a47.y * s1.y + a47.z * s1.z + a47.w * s1.w;
        float dp0 = a03.x * d0.x + a03.y * d0.y + a03.z * d0.z + a03.w * d0.w;
        float dp1 = a47.x * d1.x + a47.y * d1.y + a47.z * d1.z + a47.w * d1.w;
#pragma unroll
        for (int off = 16; off; off >>= 1) {
            sp0 += __shfl_xor_sync(0xffffffffu, sp0, off);
            sp1 += __shfl_xor_sync(0xffffffffu, sp1, off);
            dp0 += __shfl_xor_sync(0xffffffffu, dp0, off);
            dp1 += __shfl_xor_sync(0xffffffffu, dp1, off);
        }
        if (node < NN) {
            g_xw4[(size_t)node * 64 + lane]      = a03;
            g_xw4[(size_t)node * 64 + 32 + lane] = a47;
            if (lane == 0) {
                g_as[2 * node]     = sp0;
                g_as[2 * node + 1] = sp1;
                g_ad[2 * node]     = dp0;
                g_ad[2 * node + 1] = dp1;
            }
        }
    }
}

// scan stage 2+3 fused
__global__ void k_scanB() {
    __shared__ int sb[256];
    __shared__ int sp[256];
    int t = threadIdx.x;
    int b = blockIdx.x;

    sb[t] = (t < NB_SCAN) ? g_bsum[t] : 0;
    __syncthreads();
    for (int off = 1; off < 256; off <<= 1) {
        int u = (t >= off) ? sb[t - off] : 0;
        __syncthreads();
        sb[t] += u;
        __syncthreads();
    }
    int base = (b == 0) ? 0 : sb[b - 1];

    int i = b * 256 + t;
    int v = (i < NN) ? g_deg[i] : 0;
    sp[t] = v;
    __syncthreads();
    for (int off = 1; off < 256; off <<= 1) {
        int u = (t >= off) ? sp[t - off] : 0;
        __syncthreads();
        sp[t] += u;
        __syncthreads();
    }
    int excl = sp[t] - v + base;
    if (i < NN) { g_off[i] = excl; g_woff[i] = excl; }
}

// scatter: sources grouped by target
__global__ void k_scatter(const int* __restrict__ ei) {
    int e = blockIdx.x * blockDim.x + threadIdx.x;
    if (e >= TOTE) return;
    int s, t;
    if (e < EE) { s = ei[e]; t = ei[EE + e]; }
    else        { s = t = e - EE; }
    if ((unsigned)t >= NN || (unsigned)s >= NN) return;
    int pos = atomicAdd(&g_woff[t], 1);
    if ((unsigned)pos < TOTE) g_srcs[pos] = s;
}

// fused node kernel, 2 warps per node (one per head). lane owns 4 cols.
// gather loop unrolled x4: four independent loads in flight (MLP=4).
__global__ void k_node(const float* __restrict__ bias, const float* __restrict__ fcw,
                       const float* __restrict__ fcb) {
    __shared__ float zpart[8][3];
    int tid  = threadIdx.x;
    int lane = tid & 31;
    int winb = tid >> 5;
    int gw   = blockIdx.x * 8 + winb;
    int n    = gw >> 1;
    int h    = gw & 1;

    int off = g_off[n], deg = g_deg[n];
    float adh = g_ad[2 * n + h];

    float mas = -INFINITY;
    for (int i = lane; i < deg; i += 32)
        mas = fmaxf(mas, g_as[2 * g_srcs[off + i] + h]);
#pragma unroll
    for (int o = 16; o; o >>= 1)
        mas = fmaxf(mas, __shfl_xor_sync(0xffffffffu, mas, o));
    float m = mas + adh; m = m > 0.f ? m : 0.2f * m;

    float4 acc = make_float4(0.f, 0.f, 0.f, 0.f);
    float den = 0.f;
    const float4* xwb = g_xw4 + h * 32 + lane;

    for (int i0 = 0; i0 < deg; i0 += 32) {
        int cnt = min(32, deg - i0);
        int s = 0; float ex = 0.f;
        if (lane < cnt) {
            s = g_srcs[off + i0 + lane];
            float l = g_as[2 * s + h] + adh; l = l > 0.f ? l : 0.2f * l;
            ex = expf(l - m);
        }
        den += ex;

        int j = 0;
        for (; j + 4 <= cnt; j += 4) {
            int s0 = __shfl_sync(0xffffffffu, s, j);
            int s1 = __shfl_sync(0xffffffffu, s, j + 1);
            int s2 = __shfl_sync(0xffffffffu, s, j + 2);
            int s3 = __shfl_sync(0xffffffffu, s, j + 3);
            float4 v0 = xwb[(size_t)s0 * 64];
            float4 v1 = xwb[(size_t)s1 * 64];
            float4 v2 = xwb[(size_t)s2 * 64];
            float4 v3 = xwb[(size_t)s3 * 64];
            float e0 = __shfl_sync(0xffffffffu, ex, j);
            float e1 = __shfl_sync(0xffffffffu, ex, j + 1);
            float e2 = __shfl_sync(0xffffffffu, ex, j + 2);
            float e3 = __shfl_sync(0xffffffffu, ex, j + 3);
            acc.x += e0 * v0.x; acc.y += e0 * v0.y; acc.z += e0 * v0.z; acc.w += e0 * v0.w;
            acc.x += e1 * v1.x; acc.y += e1 * v1.y; acc.z += e1 * v1.z; acc.w += e1 * v1.w;
            acc.x += e2 * v2.x; acc.y += e2 * v2.y; acc.z += e2 * v2.z; acc.w += e2 * v2.w;
            acc.x += e3 * v3.x; acc.y += e3 * v3.y; acc.z += e3 * v3.z; acc.w += e3 * v3.w;
        }
        for (; j < cnt; j++) {
            int sj = __shfl_sync(0xffffffffu, s, j);
            float4 v = xwb[(size_t)sj * 64];
            float e = __shfl_sync(0xffffffffu, ex, j);
            acc.x += e * v.x; acc.y += e * v.y; acc.z += e * v.z; acc.w += e * v.w;
        }
    }
#pragma unroll
    for (int o = 16; o; o >>= 1)
        den += __shfl_xor_sync(0xffffffffu, den, o);
    float inv = 1.f / den;

    int cb = h * 128 + lane * 4;
    float4 b4 = *(const float4*)&bias[cb];
    float vv[4] = {acc.x * inv + b4.x, acc.y * inv + b4.y,
                   acc.z * inv + b4.z, acc.w * inv + b4.w};
    float z0 = 0.f, z1 = 0.f, z2 = 0.f;
#pragma unroll
    for (int mth = 0; mth < 4; mth++) {
        float val = vv[mth] > 0.f ? vv[mth] : 0.f;
        int k = cb + mth;
        z0 += val * fcw[k * 3 + 0];
        z1 += val * fcw[k * 3 + 1];
        z2 += val * fcw[k * 3 + 2];
    }
#pragma unroll
    for (int o = 16; o; o >>= 1) {
        z0 += __shfl_xor_sync(0xffffffffu, z0, o);
        z1 += __shfl_xor_sync(0xffffffffu, z1, o);
        z2 += __shfl_xor_sync(0xffffffffu, z2, o);
    }
    if (lane == 0) { zpart[winb][0] = z0; zpart[winb][1] = z1; zpart[winb][2] = z2; }
    __syncthreads();
    if (h == 0 && lane == 0) {
        float p0 = zpart[winb][0] + zpart[winb + 1][0] + fcb[0];
        float p1 = zpart[winb][1] + zpart[winb + 1][1] + fcb[1];
        float p2 = zpart[winb][2] + zpart[winb + 1][2] + fcb[2];
        float mx = fmaxf(p0, fmaxf(p1, p2));
        float ls = mx + logf(expf(p0 - mx) + expf(p1 - mx) + expf(p2 - mx));
        g_z[n * 3 + 0] = p0 - ls;
        g_z[n * 3 + 1] = p1 - ls;
        g_z[n * 3 + 2] = p2 - ls;
    }
}

// deterministic pool: batch sorted -> contiguous node range per graph.
__global__ void k_pool(const int* __restrict__ batch, const float* __restrict__ a,
                       float* __restrict__ out) {
    __shared__ float sz[3][256];
    int g = blockIdx.x;
    int t = threadIdx.x;
    int lo = 0, hi = NN;
    while (lo < hi) { int mid = (lo + hi) >> 1; if (batch[mid] < g) lo = mid + 1; else hi = mid; }
    int s0 = lo;
    hi = NN;
    while (lo < hi) { int mid = (lo + hi) >> 1; if (batch[mid] < g + 1) lo = mid + 1; else hi = mid; }
    int e0 = lo;

    float z0 = 0.f, z1 = 0.f, z2 = 0.f;
    for (int n = s0 + t; n < e0; n += 256) {
        z0 += g_z[n * 3 + 0];
        z1 += g_z[n * 3 + 1];
        z2 += g_z[n * 3 + 2];
    }
    sz[0][t] = z0; sz[1][t] = z1; sz[2][t] = z2;
    __syncthreads();
    for (int off = 128; off; off >>= 1) {
        if (t < off) {
            sz[0][t] += sz[0][t + off];
            sz[1][t] += sz[1][t + off];
            sz[2][t] += sz[2][t + off];
        }
        __syncthreads();
    }
    if (t == 0) {
        float sc = *a;
        float p0 = sc * sz[0][0], p1 = sc * sz[1][0], p2 = sc * sz[2][0];
        float mx = fmaxf(p0, fmaxf(p1, p2));
        float ls = mx + logf(expf(p0 - mx) + expf(p1 - mx) + expf(p2 - mx));
        out[g * 3 + 0] = p0 - ls;
        out[g * 3 + 1] = p1 - ls;
        out[g * 3 + 2] = p2 - ls;
    }
}

// ---------------- launch -----------------------------------------------------
extern "C" void kernel_launch(void* const* d_in, const int* in_sizes, int n_in,
                              void* d_out, int out_size) {
    const float* x     = (const float*)d_in[0];
    const int*   ei    = (const int*)d_in[1];
    const int*   batch = (const int*)d_in[2];
    const float* W     = (const float*)d_in[3];
    const float* att_s = (const float*)d_in[4];
    const float* att_d = (const float*)d_in[5];
    const float* bias  = (const float*)d_in[6];
    const float* fcw   = (const float*)d_in[7];
    const float* fcb   = (const float*)d_in[8];
    const float* a     = (const float*)d_in[9];
    float* out = (float*)d_out;

    static cudaStream_t s2 = 0;
    static cudaEvent_t evA = 0, evB = 0;
    if (s2 == 0) {
        cudaStreamCreateWithFlags(&s2, cudaStreamNonBlocking);
        cudaEventCreateWithFlags(&evA, cudaEventDisableTiming);
        cudaEventCreateWithFlags(&evB, cudaEventDisableTiming);
        cudaFuncSetAttribute(k_gemm, cudaFuncAttributeMaxDynamicSharedMemorySize, GSM);
    }

    // main: init -> wprep -> gemm ; side stream: CSR chain. gemm = 4th launch.
    k_init   <<<(NN + 255) / 256, 256>>>();
    cudaEventRecord(evA, 0);
    k_wprep  <<<128, 256>>>(W);
    cudaStreamWaitEvent(s2, evA, 0);
    k_deg    <<<(TOTE + 255) / 256, 256, 0, s2>>>(ei);
    k_gemm   <<<(NN + 63) / 64, 256, GSM>>>(x, att_s, att_d);   // 4th submission: profiled
    k_scan1  <<<NB_SCAN, 256, 0, s2>>>();
    k_scanB  <<<NB_SCAN, 256, 0, s2>>>();
    k_scatter<<<(TOTE + 255) / 256, 256, 0, s2>>>(ei);
    cudaEventRecord(evB, s2);
    cudaStreamWaitEvent(0, evB, 0);
    k_node   <<<(NN * 2) / 8, 256>>>(bias, fcw, fcb);
    k_pool   <<<GG, 256>>>(batch, a, out);
}

// round 15
// speedup vs baseline: 1.3041x; 1.0724x over previous
#include <cuda_runtime.h>
#include <cuda_bf16.h>
#include <math.h>

#define NN   50000
#define EE   300000
#define TOTE (EE + NN)
#define GG   64
#define NB_SCAN 196   // ceil(NN/256)

typedef unsigned int u32;

// ---------------- scratch (device globals; no allocation allowed) ----------
__device__ float4 g_xw4[NN * 64];   // x @ W   [N, 256] viewed as [N, 64] float4
__device__ float  g_as[NN * 2];
__device__ float  g_ad[NN * 2];
__device__ int    g_deg[NN];
__device__ int    g_off[NN];
__device__ int    g_woff[NN];
__device__ int    g_srcs[TOTE];
__device__ float  g_z[NN * 3];
__device__ int    g_bsum[256];
__device__ uint4  g_wfrag[8192];    // W in mma B-frag order [ks][cg][ct][lane]

// ---------------- helpers -----------------------------------------------------
__device__ __forceinline__ u32 pack_hi(float a, float b, float& la, float& lb) {
    __nv_bfloat16 ha = __float2bfloat16(a), hb = __float2bfloat16(b);
    la = a - __bfloat162float(ha);
    lb = b - __bfloat162float(hb);
    return (u32)__bfloat16_as_ushort(ha) | ((u32)__bfloat16_as_ushort(hb) << 16);
}
__device__ __forceinline__ u32 pack_bf(float a, float b) {
    return (u32)__bfloat16_as_ushort(__float2bfloat16(a)) |
           ((u32)__bfloat16_as_ushort(__float2bfloat16(b)) << 16);
}
__device__ __forceinline__ void mma_bf16(float* d, u32 a0, u32 a1, u32 a2, u32 a3,
                                         u32 b0, u32 b1) {
    asm volatile(
        "mma.sync.aligned.m16n8k16.row.col.f32.bf16.bf16.f32 "
        "{%0,%1,%2,%3}, {%4,%5,%6,%7}, {%8,%9}, {%0,%1,%2,%3};"
        : "+f"(d[0]), "+f"(d[1]), "+f"(d[2]), "+f"(d[3])
        : "r"(a0), "r"(a1), "r"(a2), "r"(a3), "r"(b0), "r"(b1));
}

// ---------------- kernels ----------------------------------------------------
__global__ void k_init() {
    int i = blockIdx.x * blockDim.x + threadIdx.x;
    if (i < NN) g_deg[i] = 0;
}

// W prep: bf16 hi/lo split directly into mma B-fragment layout.
// frag i = ((ks*2 + cg)*16 + ct)*32 + lane : col = cg*128+ct*8+(lane>>2),
// k = ks*16 + {2t,2t+1,2t+8,2t+9}, t = lane&3.
__global__ void k_wprep(const float* __restrict__ W) {
    int i = blockIdx.x * 256 + threadIdx.x;
    if (i >= 8192) return;
    int lane = i & 31, ct = (i >> 5) & 15, cg = (i >> 9) & 1, ks = i >> 10;
    int col = cg * 128 + ct * 8 + (lane >> 2);
    int t = lane & 3;
    int k0 = ks * 16 + 2 * t;
    float v0 = W[(k0 + 0) * 256 + col];
    float v1 = W[(k0 + 1) * 256 + col];
    float v2 = W[(k0 + 8) * 256 + col];
    float v3 = W[(k0 + 9) * 256 + col];
    float l0, l1, l2, l3;
    u32 bh0 = pack_hi(v0, v1, l0, l1);
    u32 bh1 = pack_hi(v2, v3, l2, l3);
    u32 bl0 = pack_bf(l0, l1);
    u32 bl1 = pack_bf(l2, l3);
    g_wfrag[i] = make_uint4(bh0, bh1, bl0, bl1);
}

// degree histogram of targets
__global__ void k_deg(const int* __restrict__ ei) {
    int e = blockIdx.x * blockDim.x + threadIdx.x;
    if (e >= TOTE) return;
    int t = (e < EE) ? ei[EE + e] : (e - EE);
    if ((unsigned)t < NN) atomicAdd(&g_deg[t], 1);
}

// scan stage 1: per-block sums
__global__ void k_scan1() {
    __shared__ int sp[256];
    int t = threadIdx.x;
    int i = blockIdx.x * 256 + t;
    sp[t] = (i < NN) ? g_deg[i] : 0;
    __syncthreads();
    for (int off = 128; off; off >>= 1) {
        if (t < off) sp[t] += sp[t + off];
        __syncthreads();
    }
    if (t == 0) g_bsum[blockIdx.x] = sp[0];
}

// Tensor-core GEMM, split-precision bf16 (hi*hi + hi*lo + lo*hi).
// Block = 64 nodes; warp = 16 nodes x 128 cols (one head). W fragments
// LDG'd directly from g_wfrag (no W smem, single barrier before compute).
#define XHO 0
#define XLO 17408
#define GSM 66560          // D drain tile [64][260] floats (aliases x region)
__global__ __launch_bounds__(256) void k_gemm(const float* __restrict__ x,
                                              const float* __restrict__ att_s,
                                              const float* __restrict__ att_d) {
    extern __shared__ char smc[];
    int tid  = threadIdx.x;
    int lane = tid & 31;
    int w    = tid >> 5;
    int ng   = w >> 1, cg = w & 1;    // node group 0..3, col group (=head) 0..1
    int g    = lane >> 2, t = lane & 3;
    int n0   = blockIdx.x * 64;

    // x fill: 64 nodes x 128 feats -> bf16 hi/lo, row pitch 272B
#pragma unroll
    for (int r = 0; r < 8; r++) {
        int lin4 = r * 256 + tid;
        int node = lin4 >> 5, kq = lin4 & 31;
        float4 v = make_float4(0.f, 0.f, 0.f, 0.f);
        if (n0 + node < NN) v = ((const float4*)x)[(size_t)(n0 + node) * 32 + kq];
        float lx, ly, lz, lw;
        u32 h01 = pack_hi(v.x, v.y, lx, ly);
        u32 h23 = pack_hi(v.z, v.w, lz, lw);
        u32 l01 = pack_bf(lx, ly), l23 = pack_bf(lz, lw);
        int off = node * 272 + kq * 8;
        *(u32*)(smc + XHO + off)     = h01;
        *(u32*)(smc + XHO + off + 4) = h23;
        *(u32*)(smc + XLO + off)     = l01;
        *(u32*)(smc + XLO + off + 4) = l23;
    }
    __syncthreads();

    float acc[16][4];
#pragma unroll
    for (int ct = 0; ct < 16; ct++)
#pragma unroll
        for (int c = 0; c < 4; c++) acc[ct][c] = 0.f;

    const uint4* wf = g_wfrag + cg * 512 + lane;
    for (int ks = 0; ks < 8; ks++) {
        // A fragments (rows ng*16+g / +8, k = ks*16 + {2t, 2t+8})
        int ab = XHO + (ng * 16 + g) * 272 + ks * 32 + 4 * t;
        u32 ah0 = *(u32*)(smc + ab),        ah1 = *(u32*)(smc + ab + 2176);
        u32 ah2 = *(u32*)(smc + ab + 16),   ah3 = *(u32*)(smc + ab + 2192);
        int abl = ab + (XLO - XHO);
        u32 al0 = *(u32*)(smc + abl),       al1 = *(u32*)(smc + abl + 2176);
        u32 al2 = *(u32*)(smc + abl + 16),  al3 = *(u32*)(smc + abl + 2192);
#pragma unroll
        for (int ct = 0; ct < 16; ct++) {
            uint4 b = wf[ks * 1024 + ct * 32];
            mma_bf16(acc[ct], ah0, ah1, ah2, ah3, b.x, b.y);
            mma_bf16(acc[ct], ah0, ah1, ah2, ah3, b.z, b.w);
            mma_bf16(acc[ct], al0, al1, al2, al3, b.x, b.y);
        }
    }
    __syncthreads();

    // drain fragments -> smem D tile [64][260 floats]
#pragma unroll
    for (int ct = 0; ct < 16; ct++) {
        int row = ng * 16 + g, col = cg * 128 + ct * 8 + 2 * t;
        *(float2*)(smc + (row * 260 + col) * 4)       = make_float2(acc[ct][0], acc[ct][1]);
        *(float2*)(smc + ((row + 8) * 260 + col) * 4) = make_float2(acc[ct][2], acc[ct][3]);
    }
    __syncthreads();

    // epilogue: coalesced store + fused a_s/a_d (warp = 8 nodes)
    float4 s0 = *(const float4*)&att_s[lane * 4];
    float4 s1 = *(const float4*)&att_s[128 + lane * 4];
    float4 d0 = *(const float4*)&att_d[lane * 4];
    float4 d1 = *(const float4*)&att_d[128 + lane * 4];
#pragma unroll
    for (int i = 0; i < 8; i++) {
        int rowl = w * 8 + i;
        float4 a03 = *(float4*)(smc + (rowl * 260 + lane * 4) * 4);
        float4 a47 = *(float4*)(smc + (rowl * 260 + 128 + lane * 4) * 4);
        int node = n0 + rowl;
        float sp0 = a03.x * s0.x + a03.y * s0.y + a03.z * s0.z + a03.w * s0.w;
        float sp1 = a47.x * s1.x + a47.y * s1.y + a47.z * s1.z + a47.w * s1.w;
        float dp0 = a03.x * d0.x + a03.y * d0.y + a03.z * d0.z + a03.w * d0.w;
        float dp1 = a47.x * d1.x + a47.y * d1.y + a47.z * d1.z + a47.w * d1.w;
#pragma unroll
        for (int off = 16; off; off >>= 1) {
            sp0 += __shfl_xor_sync(0xffffffffu, sp0, off);
            sp1 += __shfl_xor_sync(0xffffffffu, sp1, off);
            dp0 += __shfl_xor_sync(0xffffffffu, dp0, off);
            dp1 += __shfl_xor_sync(0xffffffffu, dp1, off);
        }
        if (node < NN) {
            g_xw4[(size_t)node * 64 + lane]      = a03;
            g_xw4[(size_t)node * 64 + 32 + lane] = a47;
            if (lane == 0) {
                g_as[2 * node]     = sp0;
                g_as[2 * node + 1] = sp1;
                g_ad[2 * node]     = dp0;
                g_ad[2 * node + 1] = dp1;
            }
        }
    }
}

// scan stage 2+3 fused
__global__ void k_scanB() {
    __shared__ int sb[256];
    __shared__ int sp[256];
    int t = threadIdx.x;
    int b = blockIdx.x;

    sb[t] = (t < NB_SCAN) ? g_bsum[t] : 0;
    __syncthreads();
    for (int off = 1; off < 256; off <<= 1) {
        int u = (t >= off) ? sb[t - off] : 0;
        __syncthreads();
        sb[t] += u;
        __syncthreads();
    }
    int base = (b == 0) ? 0 : sb[b - 1];

    int i = b * 256 + t;
    int v = (i < NN) ? g_deg[i] : 0;
    sp[t] = v;
    __syncthreads();
    for (int off = 1; off < 256; off <<= 1) {
        int u = (t >= off) ? sp[t - off] : 0;
        __syncthreads();
        sp[t] += u;
        __syncthreads();
    }
    int excl = sp[t] - v + base;
    if (i < NN) { g_off[i] = excl; g_woff[i] = excl; }
}

// scatter: sources grouped by target
__global__ void k_scatter(const int* __restrict__ ei) {
    int e = blockIdx.x * blockDim.x + threadIdx.x;
    if (e >= TOTE) return;
    int s, t;
    if (e < EE) { s = ei[e]; t = ei[EE + e]; }
    else        { s = t = e - EE; }
    if ((unsigned)t >= NN || (unsigned)s >= NN) return;
    int pos = atomicAdd(&g_woff[t], 1);
    if ((unsigned)pos < TOTE) g_srcs[pos] = s;
}

// fused node kernel, 2 warps per node (one per head). lane owns 4 cols.
// deg<=32 fast path: fused logit load + clamped 4-wide gather (no serial tail).
__global__ void k_node(const float* __restrict__ bias, const float* __restrict__ fcw,
                       const float* __restrict__ fcb) {
    __shared__ float zpart[8][3];
    int tid  = threadIdx.x;
    int lane = tid & 31;
    int winb = tid >> 5;
    int gw   = blockIdx.x * 8 + winb;
    int n    = gw >> 1;
    int h    = gw & 1;

    int off = g_off[n], deg = g_deg[n];
    float adh = g_ad[2 * n + h];
    const float4* xwb = g_xw4 + h * 32 + lane;

    float4 acc = make_float4(0.f, 0.f, 0.f, 0.f);
    float den = 0.f;

    if (deg <= 32) {
        int s = 0; float l = -INFINITY;
        if (lane < deg) {
            s = g_srcs[off + lane];
            l = g_as[2 * s + h] + adh;
            l = l > 0.f ? l : 0.2f * l;
        }
        float m = l;
#pragma unroll
        for (int o = 16; o; o >>= 1)
            m = fmaxf(m, __shfl_xor_sync(0xffffffffu, m, o));
        float ex = (lane < deg) ? expf(l - m) : 0.f;
        den = ex;
#pragma unroll
        for (int o = 16; o; o >>= 1)
            den += __shfl_xor_sync(0xffffffffu, den, o);

        for (int j = 0; j < deg; j += 4) {
            int j1 = min(j + 1, deg - 1), j2 = min(j + 2, deg - 1), j3 = min(j + 3, deg - 1);
            int s0 = __shfl_sync(0xffffffffu, s, j);
            int s1 = __shfl_sync(0xffffffffu, s, j1);
            int s2 = __shfl_sync(0xffffffffu, s, j2);
            int s3 = __shfl_sync(0xffffffffu, s, j3);
            float4 v0 = xwb[(size_t)s0 * 64];
            float4 v1 = xwb[(size_t)s1 * 64];
            float4 v2 = xwb[(size_t)s2 * 64];
            float4 v3 = xwb[(size_t)s3 * 64];
            float e0 = __shfl_sync(0xffffffffu, ex, j);
            float e1 = (j + 1 < deg) ? __shfl_sync(0xffffffffu, ex, j1) : 0.f;
            float e2 = (j + 2 < deg) ? __shfl_sync(0xffffffffu, ex, j2) : 0.f;
            float e3 = (j + 3 < deg) ? __shfl_sync(0xffffffffu, ex, j3) : 0.f;
            acc.x += e0 * v0.x; acc.y += e0 * v0.y; acc.z += e0 * v0.z; acc.w += e0 * v0.w;
            acc.x += e1 * v1.x; acc.y += e1 * v1.y; acc.z += e1 * v1.z; acc.w += e1 * v1.w;
            acc.x += e2 * v2.x; acc.y += e2 * v2.y; acc.z += e2 * v2.z; acc.w += e2 * v2.w;
            acc.x += e3 * v3.x; acc.y += e3 * v3.y; acc.z += e3 * v3.z; acc.w += e3 * v3.w;
        }
    } else {
        // slow path: two-pass (rare)
        float mas = -INFINITY;
        for (int i = lane; i < deg; i += 32)
            mas = fmaxf(mas, g_as[2 * g_srcs[off + i] + h]);
#pragma unroll
        for (int o = 16; o; o >>= 1)
            mas = fmaxf(mas, __shfl_xor_sync(0xffffffffu, mas, o));
        float m = mas + adh; m = m > 0.f ? m : 0.2f * m;

        for (int i0 = 0; i0 < deg; i0 += 32) {
            int cnt = min(32, deg - i0);
            int s = 0; float ex = 0.f;
            if (lane < cnt) {
                s = g_srcs[off + i0 + lane];
                float l = g_as[2 * s + h] + adh; l = l > 0.f ? l : 0.2f * l;
                ex = expf(l - m);
            }
            den += ex;
            for (int j = 0; j < cnt; j += 4) {
                int j1 = min(j + 1, cnt - 1), j2 = min(j + 2, cnt - 1), j3 = min(j + 3, cnt - 1);
                int s0 = __shfl_sync(0xffffffffu, s, j);
                int s1 = __shfl_sync(0xffffffffu, s, j1);
                int s2 = __shfl_sync(0xffffffffu, s, j2);
                int s3 = __shfl_sync(0xffffffffu, s, j3);
                float4 v0 = xwb[(size_t)s0 * 64];
                float4 v1 = xwb[(size_t)s1 * 64];
                float4 v2 = xwb[(size_t)s2 * 64];
                float4 v3 = xwb[(size_t)s3 * 64];
                float e0 = __shfl_sync(0xffffffffu, ex, j);
                float e1 = (j + 1 < cnt) ? __shfl_sync(0xffffffffu, ex, j1) : 0.f;
                float e2 = (j + 2 < cnt) ? __shfl_sync(0xffffffffu, ex, j2) : 0.f;
                float e3 = (j + 3 < cnt) ? __shfl_sync(0xffffffffu, ex, j3) : 0.f;
                acc.x += e0 * v0.x; acc.y += e0 * v0.y; acc.z += e0 * v0.z; acc.w += e0 * v0.w;
                acc.x += e1 * v1.x; acc.y += e1 * v1.y; acc.z += e1 * v1.z; acc.w += e1 * v1.w;
                acc.x += e2 * v2.x; acc.y += e2 * v2.y; acc.z += e2 * v2.z; acc.w += e2 * v2.w;
                acc.x += e3 * v3.x; acc.y += e3 * v3.y; acc.z += e3 * v3.z; acc.w += e3 * v3.w;
            }
        }
#pragma unroll
        for (int o = 16; o; o >>= 1)
            den += __shfl_xor_sync(0xffffffffu, den, o);
    }
    float inv = 1.f / den;

    int cb = h * 128 + lane * 4;
    float4 b4 = *(const float4*)&bias[cb];
    float vv[4] = {acc.x * inv + b4.x, acc.y * inv + b4.y,
                   acc.z * inv + b4.z, acc.w * inv + b4.w};
    float z0 = 0.f, z1 = 0.f, z2 = 0.f;
#pragma unroll
    for (int mth = 0; mth < 4; mth++) {
        float val = vv[mth] > 0.f ? vv[mth] : 0.f;
        int k = cb + mth;
        z0 += val * fcw[k * 3 + 0];
        z1 += val * fcw[k * 3 + 1];
        z2 += val * fcw[k * 3 + 2];
    }
#pragma unroll
    for (int o = 16; o; o >>= 1) {
        z0 += __shfl_xor_sync(0xffffffffu, z0, o);
        z1 += __shfl_xor_sync(0xffffffffu, z1, o);
        z2 += __shfl_xor_sync(0xffffffffu, z2, o);
    }
    if (lane == 0) { zpart[winb][0] = z0; zpart[winb][1] = z1; zpart[winb][2] = z2; }
    __syncthreads();
    if (h == 0 && lane == 0) {
        float p0 = zpart[winb][0] + zpart[winb + 1][0] + fcb[0];
        float p1 = zpart[winb][1] + zpart[winb + 1][1] + fcb[1];
        float p2 = zpart[winb][2] + zpart[winb + 1][2] + fcb[2];
        float mx = fmaxf(p0, fmaxf(p1, p2));
        float ls = mx + logf(expf(p0 - mx) + expf(p1 - mx) + expf(p2 - mx));
        g_z[n * 3 + 0] = p0 - ls;
        g_z[n * 3 + 1] = p1 - ls;
        g_z[n * 3 + 2] = p2 - ls;
    }
}

// deterministic pool: batch sorted -> contiguous node range per graph.
__global__ void k_pool(const int* __restrict__ batch, const float* __restrict__ a,
                       float* __restrict__ out) {
    __shared__ float sz[3][256];
    int g = blockIdx.x;
    int t = threadIdx.x;
    int lo = 0, hi = NN;
    while (lo < hi) { int mid = (lo + hi) >> 1; if (batch[mid] < g) lo = mid + 1; else hi = mid; }
    int s0 = lo;
    hi = NN;
    while (lo < hi) { int mid = (lo + hi) >> 1; if (batch[mid] < g + 1) lo = mid + 1; else hi = mid; }
    int e0 = lo;

    float z0 = 0.f, z1 = 0.f, z2 = 0.f;
    for (int n = s0 + t; n < e0; n += 256) {
        z0 += g_z[n * 3 + 0];
        z1 += g_z[n * 3 + 1];
        z2 += g_z[n * 3 + 2];
    }
    sz[0][t] = z0; sz[1][t] = z1; sz[2][t] = z2;
    __syncthreads();
    for (int off = 128; off; off >>= 1) {
        if (t < off) {
            sz[0][t] += sz[0][t + off];
            sz[1][t] += sz[1][t + off];
            sz[2][t] += sz[2][t + off];
        }
        __syncthreads();
    }
    if (t == 0) {
        float sc = *a;
        float p0 = sc * sz[0][0], p1 = sc * sz[1][0], p2 = sc * sz[2][0];
        float mx = fmaxf(p0, fmaxf(p1, p2));
        float ls = mx + logf(expf(p0 - mx) + expf(p1 - mx) + expf(p2 - mx));
        out[g * 3 + 0] = p0 - ls;
        out[g * 3 + 1] = p1 - ls;
        out[g * 3 + 2] = p2 - ls;
    }
}

// ---------------- launch -----------------------------------------------------
extern "C" void kernel_launch(void* const* d_in, const int* in_sizes, int n_in,
                              void* d_out, int out_size) {
    const float* x     = (const float*)d_in[0];
    const int*   ei    = (const int*)d_in[1];
    const int*   batch = (const int*)d_in[2];
    const float* W     = (const float*)d_in[3];
    const float* att_s = (const float*)d_in[4];
    const float* att_d = (const float*)d_in[5];
    const float* bias  = (const float*)d_in[6];
    const float* fcw   = (const float*)d_in[7];
    const float* fcb   = (const float*)d_in[8];
    const float* a     = (const float*)d_in[9];
    float* out = (float*)d_out;

    static cudaStream_t s2 = 0;
    static cudaEvent_t evA = 0, evB = 0;
    if (s2 == 0) {
        cudaStreamCreateWithFlags(&s2, cudaStreamNonBlocking);
        cudaEventCreateWithFlags(&evA, cudaEventDisableTiming);
        cudaEventCreateWithFlags(&evB, cudaEventDisableTiming);
        cudaFuncSetAttribute(k_gemm, cudaFuncAttributeMaxDynamicSharedMemorySize, GSM);
    }

    // main: init -> wprep -> gemm ; side stream: CSR chain. gemm = 4th launch.
    k_init   <<<(NN + 255) / 256, 256>>>();
    cudaEventRecord(evA, 0);
    k_wprep  <<<32, 256>>>(W);
    cudaStreamWaitEvent(s2, evA, 0);
    k_deg    <<<(TOTE + 255) / 256, 256, 0, s2>>>(ei);
    k_gemm   <<<(NN + 63) / 64, 256, GSM>>>(x, att_s, att_d);   // 4th submission: profiled
    k_scan1  <<<NB_SCAN, 256, 0, s2>>>();
    k_scanB  <<<NB_SCAN, 256, 0, s2>>>();
    k_scatter<<<(TOTE + 255) / 256, 256, 0, s2>>>(ei);
    cudaEventRecord(evB, s2);
    cudaStreamWaitEvent(0, evB, 0);
    k_node   <<<(NN * 2) / 8, 256>>>(bias, fcw, fcb);
    k_pool   <<<GG, 256>>>(batch, a, out);
}

// round 16
// speedup vs baseline: 1.3318x; 1.0212x over previous
#include <cuda_runtime.h>
#include <cuda_bf16.h>
#include <math.h>

#define NN   50000
#define EE   300000
#define TOTE (EE + NN)
#define GG   64
#define NB_SCAN 196   // ceil(NN/256)

typedef unsigned int u32;

// ---------------- scratch (device globals; no allocation allowed) ----------
__device__ float4 g_xw4[NN * 64];   // x @ W   [N, 256] viewed as [N, 64] float4
__device__ float  g_as[NN * 2];
__device__ float  g_ad[NN * 2];
__device__ int    g_deg[NN];
__device__ int    g_off[NN];
__device__ int    g_woff[NN];
__device__ int    g_srcs[TOTE];
__device__ float  g_z[NN * 3];
__device__ int    g_bsum[256];
__device__ uint4  g_wfrag[8192];    // W in mma B-frag order [ks][cg][ct16][lane]

// ---------------- helpers -----------------------------------------------------
__device__ __forceinline__ u32 pack_hi(float a, float b, float& la, float& lb) {
    __nv_bfloat16 ha = __float2bfloat16(a), hb = __float2bfloat16(b);
    la = a - __bfloat162float(ha);
    lb = b - __bfloat162float(hb);
    return (u32)__bfloat16_as_ushort(ha) | ((u32)__bfloat16_as_ushort(hb) << 16);
}
__device__ __forceinline__ u32 pack_bf(float a, float b) {
    return (u32)__bfloat16_as_ushort(__float2bfloat16(a)) |
           ((u32)__bfloat16_as_ushort(__float2bfloat16(b)) << 16);
}
__device__ __forceinline__ void mma_bf16(float* d, u32 a0, u32 a1, u32 a2, u32 a3,
                                         u32 b0, u32 b1) {
    asm volatile(
        "mma.sync.aligned.m16n8k16.row.col.f32.bf16.bf16.f32 "
        "{%0,%1,%2,%3}, {%4,%5,%6,%7}, {%8,%9}, {%0,%1,%2,%3};"
        : "+f"(d[0]), "+f"(d[1]), "+f"(d[2]), "+f"(d[3])
        : "r"(a0), "r"(a1), "r"(a2), "r"(a3), "r"(b0), "r"(b1));
}

// ---------------- kernels ----------------------------------------------------
__global__ void k_init() {
    int i = blockIdx.x * blockDim.x + threadIdx.x;
    if (i < NN) g_deg[i] = 0;
}

// W prep: bf16 hi/lo split directly into mma B-fragment layout.
__global__ void k_wprep(const float* __restrict__ W) {
    int i = blockIdx.x * 256 + threadIdx.x;
    if (i >= 8192) return;
    int lane = i & 31, ct = (i >> 5) & 15, cg = (i >> 9) & 1, ks = i >> 10;
    int col = cg * 128 + ct * 8 + (lane >> 2);
    int t = lane & 3;
    int k0 = ks * 16 + 2 * t;
    float v0 = W[(k0 + 0) * 256 + col];
    float v1 = W[(k0 + 1) * 256 + col];
    float v2 = W[(k0 + 8) * 256 + col];
    float v3 = W[(k0 + 9) * 256 + col];
    float l0, l1, l2, l3;
    u32 bh0 = pack_hi(v0, v1, l0, l1);
    u32 bh1 = pack_hi(v2, v3, l2, l3);
    u32 bl0 = pack_bf(l0, l1);
    u32 bl1 = pack_bf(l2, l3);
    g_wfrag[i] = make_uint4(bh0, bh1, bl0, bl1);
}

// degree histogram of targets
__global__ void k_deg(const int* __restrict__ ei) {
    int e = blockIdx.x * blockDim.x + threadIdx.x;
    if (e >= TOTE) return;
    int t = (e < EE) ? ei[EE + e] : (e - EE);
    if ((unsigned)t < NN) atomicAdd(&g_deg[t], 1);
}

// scan stage 1: per-block sums
__global__ void k_scan1() {
    __shared__ int sp[256];
    int t = threadIdx.x;
    int i = blockIdx.x * 256 + t;
    sp[t] = (i < NN) ? g_deg[i] : 0;
    __syncthreads();
    for (int off = 128; off; off >>= 1) {
        if (t < off) sp[t] += sp[t + off];
        __syncthreads();
    }
    if (t == 0) g_bsum[blockIdx.x] = sp[0];
}

// Tensor-core GEMM, split-precision bf16 (hi*hi + hi*lo + lo*hi).
// Block = 32 nodes x 256 cols, 8 warps: ng = w>>2 (16-node group),
// cq = w&3 (64-col quarter). Warp = 16 nodes x 64 cols -> 32 acc regs
// -> 3 blocks/SM. B fragments LDG'd from g_wfrag.
#define XHO 0
#define XLO 8704
#define GSM 33280          // D drain tile [32][260] floats (aliases x region)
__global__ __launch_bounds__(256) void k_gemm(const float* __restrict__ x,
                                              const float* __restrict__ att_s,
                                              const float* __restrict__ att_d) {
    extern __shared__ char smc[];
    int tid  = threadIdx.x;
    int lane = tid & 31;
    int w    = tid >> 5;
    int ng   = w >> 2, cq = w & 3;    // node group 0..1, col quarter 0..3
    int cg   = cq >> 1;               // head
    int g    = lane >> 2, t = lane & 3;
    int n0   = blockIdx.x * 32;

    // x fill: 32 nodes x 128 feats -> bf16 hi/lo, row pitch 272B
#pragma unroll
    for (int r = 0; r < 4; r++) {
        int lin4 = r * 256 + tid;
        int node = lin4 >> 5, kq = lin4 & 31;
        float4 v = make_float4(0.f, 0.f, 0.f, 0.f);
        if (n0 + node < NN) v = ((const float4*)x)[(size_t)(n0 + node) * 32 + kq];
        float lx, ly, lz, lw;
        u32 h01 = pack_hi(v.x, v.y, lx, ly);
        u32 h23 = pack_hi(v.z, v.w, lz, lw);
        u32 l01 = pack_bf(lx, ly), l23 = pack_bf(lz, lw);
        int off = node * 272 + kq * 8;
        *(u32*)(smc + XHO + off)     = h01;
        *(u32*)(smc + XHO + off + 4) = h23;
        *(u32*)(smc + XLO + off)     = l01;
        *(u32*)(smc + XLO + off + 4) = l23;
    }
    __syncthreads();

    float acc[8][4];
#pragma unroll
    for (int ct = 0; ct < 8; ct++)
#pragma unroll
        for (int c = 0; c < 4; c++) acc[ct][c] = 0.f;

    // B fragment base: within-head col-tile ct16 = (cq&1)*8 + ct
    const uint4* wf = g_wfrag + cg * 512 + (cq & 1) * 8 * 32 + lane;
    for (int ks = 0; ks < 8; ks++) {
        // A fragments (rows ng*16+g / +8, k = ks*16 + {2t, 2t+8})
        int ab = XHO + (ng * 16 + g) * 272 + ks * 32 + 4 * t;
        u32 ah0 = *(u32*)(smc + ab),        ah1 = *(u32*)(smc + ab + 2176);
        u32 ah2 = *(u32*)(smc + ab + 16),   ah3 = *(u32*)(smc + ab + 2192);
        int abl = ab + (XLO - XHO);
        u32 al0 = *(u32*)(smc + abl),       al1 = *(u32*)(smc + abl + 2176);
        u32 al2 = *(u32*)(smc + abl + 16),  al3 = *(u32*)(smc + abl + 2192);
#pragma unroll
        for (int ct = 0; ct < 8; ct++) {
            uint4 b = wf[ks * 1024 + ct * 32];
            mma_bf16(acc[ct], ah0, ah1, ah2, ah3, b.x, b.y);
            mma_bf16(acc[ct], ah0, ah1, ah2, ah3, b.z, b.w);
            mma_bf16(acc[ct], al0, al1, al2, al3, b.x, b.y);
        }
    }
    __syncthreads();

    // drain fragments -> smem D tile [32][260 floats]
#pragma unroll
    for (int ct = 0; ct < 8; ct++) {
        int row = ng * 16 + g, col = cq * 64 + ct * 8 + 2 * t;
        *(float2*)(smc + (row * 260 + col) * 4)       = make_float2(acc[ct][0], acc[ct][1]);
        *(float2*)(smc + ((row + 8) * 260 + col) * 4) = make_float2(acc[ct][2], acc[ct][3]);
    }
    __syncthreads();

    // epilogue: coalesced store + fused a_s/a_d (warp = 4 nodes)
    float4 s0 = *(const float4*)&att_s[lane * 4];
    float4 s1 = *(const float4*)&att_s[128 + lane * 4];
    float4 d0 = *(const float4*)&att_d[lane * 4];
    float4 d1 = *(const float4*)&att_d[128 + lane * 4];
#pragma unroll
    for (int i = 0; i < 4; i++) {
        int rowl = w * 4 + i;
        float4 a03 = *(float4*)(smc + (rowl * 260 + lane * 4) * 4);
        float4 a47 = *(float4*)(smc + (rowl * 260 + 128 + lane * 4) * 4);
        int node = n0 + rowl;
        float sp0 = a03.x * s0.x + a03.y * s0.y + a03.z * s0.z + a03.w * s0.w;
        float sp1 = a47.x * s1.x + a47.y * s1.y + a47.z * s1.z + a47.w * s1.w;
        float dp0 = a03.x * d0.x + a03.y * d0.y + a03.z * d0.z + a03.w * d0.w;
        float dp1 = a47.x * d1.x + a47.y * d1.y + a47.z * d1.z + a47.w * d1.w;
#pragma unroll
        for (int off = 16; off; off >>= 1) {
            sp0 += __shfl_xor_sync(0xffffffffu, sp0, off);
            sp1 += __shfl_xor_sync(0xffffffffu, sp1, off);
            dp0 += __shfl_xor_sync(0xffffffffu, dp0, off);
            dp1 += __shfl_xor_sync(0xffffffffu, dp1, off);
        }
        if (node < NN) {
            g_xw4[(size_t)node * 64 + lane]      = a03;
            g_xw4[(size_t)node * 64 + 32 + lane] = a47;
            if (lane == 0) {
                g_as[2 * node]     = sp0;
                g_as[2 * node + 1] = sp1;
                g_ad[2 * node]     = dp0;
                g_ad[2 * node + 1] = dp1;
            }
        }
    }
}

// scan stage 2+3 fused
__global__ void k_scanB() {
    __shared__ int sb[256];
    __shared__ int sp[256];
    int t = threadIdx.x;
    int b = blockIdx.x;

    sb[t] = (t < NB_SCAN) ? g_bsum[t] : 0;
    __syncthreads();
    for (int off = 1; off < 256; off <<= 1) {
        int u = (t >= off) ? sb[t - off] : 0;
        __syncthreads();
        sb[t] += u;
        __syncthreads();
    }
    int base = (b == 0) ? 0 : sb[b - 1];

    int i = b * 256 + t;
    int v = (i < NN) ? g_deg[i] : 0;
    sp[t] = v;
    __syncthreads();
    for (int off = 1; off < 256; off <<= 1) {
        int u = (t >= off) ? sp[t - off] : 0;
        __syncthreads();
        sp[t] += u;
        __syncthreads();
    }
    int excl = sp[t] - v + base;
    if (i < NN) { g_off[i] = excl; g_woff[i] = excl; }
}

// scatter: sources grouped by target
__global__ void k_scatter(const int* __restrict__ ei) {
    int e = blockIdx.x * blockDim.x + threadIdx.x;
    if (e >= TOTE) return;
    int s, t;
    if (e < EE) { s = ei[e]; t = ei[EE + e]; }
    else        { s = t = e - EE; }
    if ((unsigned)t >= NN || (unsigned)s >= NN) return;
    int pos = atomicAdd(&g_woff[t], 1);
    if ((unsigned)pos < TOTE) g_srcs[pos] = s;
}

// fused node kernel, 2 warps per node (one per head). lane owns 4 cols.
// deg<=32 fast path: fused logit load + clamped 8-wide gather (MLP=8).
__global__ void k_node(const float* __restrict__ bias, const float* __restrict__ fcw,
                       const float* __restrict__ fcb) {
    __shared__ float zpart[8][3];
    int tid  = threadIdx.x;
    int lane = tid & 31;
    int winb = tid >> 5;
    int gw   = blockIdx.x * 8 + winb;
    int n    = gw >> 1;
    int h    = gw & 1;

    int off = g_off[n], deg = g_deg[n];
    float adh = g_ad[2 * n + h];
    const float4* xwb = g_xw4 + h * 32 + lane;

    float4 acc = make_float4(0.f, 0.f, 0.f, 0.f);
    float den = 0.f;

    if (deg <= 32) {
        int s = 0; float l = -INFINITY;
        if (lane < deg) {
            s = g_srcs[off + lane];
            l = g_as[2 * s + h] + adh;
            l = l > 0.f ? l : 0.2f * l;
        }
        float m = l;
#pragma unroll
        for (int o = 16; o; o >>= 1)
            m = fmaxf(m, __shfl_xor_sync(0xffffffffu, m, o));
        float ex = (lane < deg) ? expf(l - m) : 0.f;
        den = ex;
#pragma unroll
        for (int o = 16; o; o >>= 1)
            den += __shfl_xor_sync(0xffffffffu, den, o);

        for (int j = 0; j < deg; j += 8) {
            int jj[8];
            float4 v[8];
            float e[8];
#pragma unroll
            for (int q = 0; q < 8; q++) jj[q] = min(j + q, deg - 1);
            int ss[8];
#pragma unroll
            for (int q = 0; q < 8; q++) ss[q] = __shfl_sync(0xffffffffu, s, jj[q]);
#pragma unroll
            for (int q = 0; q < 8; q++) v[q] = xwb[(size_t)ss[q] * 64];
#pragma unroll
            for (int q = 0; q < 8; q++)
                e[q] = (j + q < deg) ? __shfl_sync(0xffffffffu, ex, jj[q]) : 0.f;
#pragma unroll
            for (int q = 0; q < 8; q++) {
                acc.x += e[q] * v[q].x; acc.y += e[q] * v[q].y;
                acc.z += e[q] * v[q].z; acc.w += e[q] * v[q].w;
            }
        }
    } else {
        // slow path: two-pass (rare)
        float mas = -INFINITY;
        for (int i = lane; i < deg; i += 32)
            mas = fmaxf(mas, g_as[2 * g_srcs[off + i] + h]);
#pragma unroll
        for (int o = 16; o; o >>= 1)
            mas = fmaxf(mas, __shfl_xor_sync(0xffffffffu, mas, o));
        float m = mas + adh; m = m > 0.f ? m : 0.2f * m;

        for (int i0 = 0; i0 < deg; i0 += 32) {
            int cnt = min(32, deg - i0);
            int s = 0; float ex = 0.f;
            if (lane < cnt) {
                s = g_srcs[off + i0 + lane];
                float l = g_as[2 * s + h] + adh; l = l > 0.f ? l : 0.2f * l;
                ex = expf(l - m);
            }
            den += ex;
            for (int j = 0; j < cnt; j += 4) {
                int j1 = min(j + 1, cnt - 1), j2 = min(j + 2, cnt - 1), j3 = min(j + 3, cnt - 1);
                int s0 = __shfl_sync(0xffffffffu, s, j);
                int s1 = __shfl_sync(0xffffffffu, s, j1);
                int s2 = __shfl_sync(0xffffffffu, s, j2);
                int s3 = __shfl_sync(0xffffffffu, s, j3);
                float4 v0 = xwb[(size_t)s0 * 64];
                float4 v1 = xwb[(size_t)s1 * 64];
                float4 v2 = xwb[(size_t)s2 * 64];
                float4 v3 = xwb[(size_t)s3 * 64];
                float e0 = __shfl_sync(0xffffffffu, ex, j);
                float e1 = (j + 1 < cnt) ? __shfl_sync(0xffffffffu, ex, j1) : 0.f;
                float e2 = (j + 2 < cnt) ? __shfl_sync(0xffffffffu, ex, j2) : 0.f;
                float e3 = (j + 3 < cnt) ? __shfl_sync(0xffffffffu, ex, j3) : 0.f;
                acc.x += e0 * v0.x; acc.y += e0 * v0.y; acc.z += e0 * v0.z; acc.w += e0 * v0.w;
                acc.x += e1 * v1.x; acc.y += e1 * v1.y; acc.z += e1 * v1.z; acc.w += e1 * v1.w;
                acc.x += e2 * v2.x; acc.y += e2 * v2.y; acc.z += e2 * v2.z; acc.w += e2 * v2.w;
                acc.x += e3 * v3.x; acc.y += e3 * v3.y; acc.z += e3 * v3.z; acc.w += e3 * v3.w;
            }
        }
#pragma unroll
        for (int o = 16; o; o >>= 1)
            den += __shfl_xor_sync(0xffffffffu, den, o);
    }
    float inv = 1.f / den;

    int cb = h * 128 + lane * 4;
    float4 b4 = *(const float4*)&bias[cb];
    float vv[4] = {acc.x * inv + b4.x, acc.y * inv + b4.y,
                   acc.z * inv + b4.z, acc.w * inv + b4.w};
    float z0 = 0.f, z1 = 0.f, z2 = 0.f;
#pragma unroll
    for (int mth = 0; mth < 4; mth++) {
        float val = vv[mth] > 0.f ? vv[mth] : 0.f;
        int k = cb + mth;
        z0 += val * fcw[k * 3 + 0];
        z1 += val * fcw[k * 3 + 1];
        z2 += val * fcw[k * 3 + 2];
    }
#pragma unroll
    for (int o = 16; o; o >>= 1) {
        z0 += __shfl_xor_sync(0xffffffffu, z0, o);
        z1 += __shfl_xor_sync(0xffffffffu, z1, o);
        z2 += __shfl_xor_sync(0xffffffffu, z2, o);
    }
    if (lane == 0) { zpart[winb][0] = z0; zpart[winb][1] = z1; zpart[winb][2] = z2; }
    __syncthreads();
    if (h == 0 && lane == 0) {
        float p0 = zpart[winb][0] + zpart[winb + 1][0] + fcb[0];
        float p1 = zpart[winb][1] + zpart[winb + 1][1] + fcb[1];
        float p2 = zpart[winb][2] + zpart[winb + 1][2] + fcb[2];
        float mx = fmaxf(p0, fmaxf(p1, p2));
        float ls = mx + logf(expf(p0 - mx) + expf(p1 - mx) + expf(p2 - mx));
        g_z[n * 3 + 0] = p0 - ls;
        g_z[n * 3 + 1] = p1 - ls;
        g_z[n * 3 + 2] = p2 - ls;
    }
}

// deterministic pool: batch sorted -> contiguous node range per graph.
__global__ void k_pool(const int* __restrict__ batch, const float* __restrict__ a,
                       float* __restrict__ out) {
    __shared__ float sz[3][256];
    int g = blockIdx.x;
    int t = threadIdx.x;
    int lo = 0, hi = NN;
    while (lo < hi) { int mid = (lo + hi) >> 1; if (batch[mid] < g) lo = mid + 1; else hi = mid; }
    int s0 = lo;
    hi = NN;
    while (lo < hi) { int mid = (lo + hi) >> 1; if (batch[mid] < g + 1) lo = mid + 1; else hi = mid; }
    int e0 = lo;

    float z0 = 0.f, z1 = 0.f, z2 = 0.f;
    for (int n = s0 + t; n < e0; n += 256) {
        z0 += g_z[n * 3 + 0];
        z1 += g_z[n * 3 + 1];
        z2 += g_z[n * 3 + 2];
    }
    sz[0][t] = z0; sz[1][t] = z1; sz[2][t] = z2;
    __syncthreads();
    for (int off = 128; off; off >>= 1) {
        if (t < off) {
            sz[0][t] += sz[0][t + off];
            sz[1][t] += sz[1][t + off];
            sz[2][t] += sz[2][t + off];
        }
        __syncthreads();
    }
    if (t == 0) {
        float sc = *a;
        float p0 = sc * sz[0][0], p1 = sc * sz[1][0], p2 = sc * sz[2][0];
        float mx = fmaxf(p0, fmaxf(p1, p2));
        float ls = mx + logf(expf(p0 - mx) + expf(p1 - mx) + expf(p2 - mx));
        out[g * 3 + 0] = p0 - ls;
        out[g * 3 + 1] = p1 - ls;
        out[g * 3 + 2] = p2 - ls;
    }
}

// ---------------- launch -----------------------------------------------------
extern "C" void kernel_launch(void* const* d_in, const int* in_sizes, int n_in,
                              void* d_out, int out_size) {
    const float* x     = (const float*)d_in[0];
    const int*   ei    = (const int*)d_in[1];
    const int*   batch = (const int*)d_in[2];
    const float* W     = (const float*)d_in[3];
    const float* att_s = (const float*)d_in[4];
    const float* att_d = (const float*)d_in[5];
    const float* bias  = (const float*)d_in[6];
    const float* fcw   = (const float*)d_in[7];
    const float* fcb   = (const float*)d_in[8];
    const float* a     = (const float*)d_in[9];
    float* out = (float*)d_out;

    static cudaStream_t s2 = 0;
    static cudaEvent_t evA = 0, evB = 0;
    if (s2 == 0) {
        cudaStreamCreateWithFlags(&s2, cudaStreamNonBlocking);
        cudaEventCreateWithFlags(&evA, cudaEventDisableTiming);
        cudaEventCreateWithFlags(&evB, cudaEventDisableTiming);
        cudaFuncSetAttribute(k_gemm, cudaFuncAttributeMaxDynamicSharedMemorySize, GSM);
    }

    // main: init -> wprep -> gemm ; side stream: CSR chain. gemm = 4th launch.
    k_init   <<<(NN + 255) / 256, 256>>>();
    cudaEventRecord(evA, 0);
    k_wprep  <<<32, 256>>>(W);
    cudaStreamWaitEvent(s2, evA, 0);
    k_deg    <<<(TOTE + 255) / 256, 256, 0, s2>>>(ei);
    k_gemm   <<<(NN + 31) / 32, 256, GSM>>>(x, att_s, att_d);   // 4th submission: profiled
    k_scan1  <<<NB_SCAN, 256, 0, s2>>>();
    k_scanB  <<<NB_SCAN, 256, 0, s2>>>();
    k_scatter<<<(TOTE + 255) / 256, 256, 0, s2>>>(ei);
    cudaEventRecord(evB, s2);
    cudaStreamWaitEvent(0, evB, 0);
    k_node   <<<(NN * 2) / 8, 256>>>(bias, fcw, fcb);
    k_pool   <<<GG, 256>>>(batch, a, out);
}

// round 17
// speedup vs baseline: 1.5680x; 1.1773x over previous
#include <cuda_runtime.h>
#include <cuda_bf16.h>
#include <cuda_fp16.h>
#include <math.h>

#define NN   50000
#define EE   300000
#define TOTE (EE + NN)
#define GG   64
#define NB_SCAN 196   // ceil(NN/256)

typedef unsigned int u32;

// ---------------- scratch (device globals; no allocation allowed) ----------
__device__ uint2  g_xwh[NN * 64];   // x @ W as half2 pairs: [node][h*32+lane] = 4 cols
__device__ float  g_as[NN * 2];
__device__ float  g_ad[NN * 2];
__device__ int    g_deg[NN];
__device__ int    g_off[NN];
__device__ int    g_woff[NN];
__device__ int    g_srcs[TOTE];
__device__ float  g_z[NN * 3];
__device__ int    g_bsum[256];
__device__ uint4  g_wfrag[8192];    // W in mma B-frag order [ks][cg][ct16][lane]

// ---------------- helpers -----------------------------------------------------
__device__ __forceinline__ u32 pack_hi(float a, float b, float& la, float& lb) {
    __nv_bfloat16 ha = __float2bfloat16(a), hb = __float2bfloat16(b);
    la = a - __bfloat162float(ha);
    lb = b - __bfloat162float(hb);
    return (u32)__bfloat16_as_ushort(ha) | ((u32)__bfloat16_as_ushort(hb) << 16);
}
__device__ __forceinline__ u32 pack_bf(float a, float b) {
    return (u32)__bfloat16_as_ushort(__float2bfloat16(a)) |
           ((u32)__bfloat16_as_ushort(__float2bfloat16(b)) << 16);
}
__device__ __forceinline__ u32 pack_h2(float a, float b) {
    __half2 h = __floats2half2_rn(a, b);
    return *reinterpret_cast<u32*>(&h);
}
__device__ __forceinline__ void mma_bf16(float* d, u32 a0, u32 a1, u32 a2, u32 a3,
                                         u32 b0, u32 b1) {
    asm volatile(
        "mma.sync.aligned.m16n8k16.row.col.f32.bf16.bf16.f32 "
        "{%0,%1,%2,%3}, {%4,%5,%6,%7}, {%8,%9}, {%0,%1,%2,%3};"
        : "+f"(d[0]), "+f"(d[1]), "+f"(d[2]), "+f"(d[3])
        : "r"(a0), "r"(a1), "r"(a2), "r"(a3), "r"(b0), "r"(b1));
}

// ---------------- kernels ----------------------------------------------------
__global__ void k_init() {
    int i = blockIdx.x * blockDim.x + threadIdx.x;
    if (i < NN) g_deg[i] = 0;
}

// W prep: bf16 hi/lo split directly into mma B-fragment layout.
__global__ void k_wprep(const float* __restrict__ W) {
    int i = blockIdx.x * 256 + threadIdx.x;
    if (i >= 8192) return;
    int lane = i & 31, ct = (i >> 5) & 15, cg = (i >> 9) & 1, ks = i >> 10;
    int col = cg * 128 + ct * 8 + (lane >> 2);
    int t = lane & 3;
    int k0 = ks * 16 + 2 * t;
    float v0 = W[(k0 + 0) * 256 + col];
    float v1 = W[(k0 + 1) * 256 + col];
    float v2 = W[(k0 + 8) * 256 + col];
    float v3 = W[(k0 + 9) * 256 + col];
    float l0, l1, l2, l3;
    u32 bh0 = pack_hi(v0, v1, l0, l1);
    u32 bh1 = pack_hi(v2, v3, l2, l3);
    u32 bl0 = pack_bf(l0, l1);
    u32 bl1 = pack_bf(l2, l3);
    g_wfrag[i] = make_uint4(bh0, bh1, bl0, bl1);
}

// degree histogram of targets
__global__ void k_deg(const int* __restrict__ ei) {
    int e = blockIdx.x * blockDim.x + threadIdx.x;
    if (e >= TOTE) return;
    int t = (e < EE) ? ei[EE + e] : (e - EE);
    if ((unsigned)t < NN) atomicAdd(&g_deg[t], 1);
}

// scan stage 1: per-block sums
__global__ void k_scan1() {
    __shared__ int sp[256];
    int t = threadIdx.x;
    int i = blockIdx.x * 256 + t;
    sp[t] = (i < NN) ? g_deg[i] : 0;
    __syncthreads();
    for (int off = 128; off; off >>= 1) {
        if (t < off) sp[t] += sp[t + off];
        __syncthreads();
    }
    if (t == 0) g_bsum[blockIdx.x] = sp[0];
}

// Tensor-core GEMM, split-precision bf16 (hi*hi + hi*lo + lo*hi).
// Block = 32 nodes x 256 cols, 8 warps. Warp = 16 nodes x 64 cols.
// Epilogue stores xw as half2 (gather copy) + fused a_s/a_d in fp32.
#define XHO 0
#define XLO 8704
#define GSM 33280          // D drain tile [32][260] floats (aliases x region)
__global__ __launch_bounds__(256) void k_gemm(const float* __restrict__ x,
                                              const float* __restrict__ att_s,
                                              const float* __restrict__ att_d) {
    extern __shared__ char smc[];
    int tid  = threadIdx.x;
    int lane = tid & 31;
    int w    = tid >> 5;
    int ng   = w >> 2, cq = w & 3;    // node group 0..1, col quarter 0..3
    int cg   = cq >> 1;               // head
    int g    = lane >> 2, t = lane & 3;
    int n0   = blockIdx.x * 32;

    // x fill: 32 nodes x 128 feats -> bf16 hi/lo, row pitch 272B
#pragma unroll
    for (int r = 0; r < 4; r++) {
        int lin4 = r * 256 + tid;
        int node = lin4 >> 5, kq = lin4 & 31;
        float4 v = make_float4(0.f, 0.f, 0.f, 0.f);
        if (n0 + node < NN) v = ((const float4*)x)[(size_t)(n0 + node) * 32 + kq];
        float lx, ly, lz, lw;
        u32 h01 = pack_hi(v.x, v.y, lx, ly);
        u32 h23 = pack_hi(v.z, v.w, lz, lw);
        u32 l01 = pack_bf(lx, ly), l23 = pack_bf(lz, lw);
        int off = node * 272 + kq * 8;
        *(u32*)(smc + XHO + off)     = h01;
        *(u32*)(smc + XHO + off + 4) = h23;
        *(u32*)(smc + XLO + off)     = l01;
        *(u32*)(smc + XLO + off + 4) = l23;
    }
    __syncthreads();

    float acc[8][4];
#pragma unroll
    for (int ct = 0; ct < 8; ct++)
#pragma unroll
        for (int c = 0; c < 4; c++) acc[ct][c] = 0.f;

    // B fragment base: within-head col-tile ct16 = (cq&1)*8 + ct
    const uint4* wf = g_wfrag + cg * 512 + (cq & 1) * 8 * 32 + lane;
    for (int ks = 0; ks < 8; ks++) {
        int ab = XHO + (ng * 16 + g) * 272 + ks * 32 + 4 * t;
        u32 ah0 = *(u32*)(smc + ab),        ah1 = *(u32*)(smc + ab + 2176);
        u32 ah2 = *(u32*)(smc + ab + 16),   ah3 = *(u32*)(smc + ab + 2192);
        int abl = ab + (XLO - XHO);
        u32 al0 = *(u32*)(smc + abl),       al1 = *(u32*)(smc + abl + 2176);
        u32 al2 = *(u32*)(smc + abl + 16),  al3 = *(u32*)(smc + abl + 2192);
#pragma unroll
        for (int ct = 0; ct < 8; ct++) {
            uint4 b = wf[ks * 1024 + ct * 32];
            mma_bf16(acc[ct], ah0, ah1, ah2, ah3, b.x, b.y);
            mma_bf16(acc[ct], ah0, ah1, ah2, ah3, b.z, b.w);
            mma_bf16(acc[ct], al0, al1, al2, al3, b.x, b.y);
        }
    }
    __syncthreads();

    // drain fragments -> smem D tile [32][260 floats]
#pragma unroll
    for (int ct = 0; ct < 8; ct++) {
        int row = ng * 16 + g, col = cq * 64 + ct * 8 + 2 * t;
        *(float2*)(smc + (row * 260 + col) * 4)       = make_float2(acc[ct][0], acc[ct][1]);
        *(float2*)(smc + ((row + 8) * 260 + col) * 4) = make_float2(acc[ct][2], acc[ct][3]);
    }
    __syncthreads();

    // epilogue: half2 gather-copy store + fused a_s/a_d (warp = 4 nodes)
    float4 s0 = *(const float4*)&att_s[lane * 4];
    float4 s1 = *(const float4*)&att_s[128 + lane * 4];
    float4 d0 = *(const float4*)&att_d[lane * 4];
    float4 d1 = *(const float4*)&att_d[128 + lane * 4];
#pragma unroll
    for (int i = 0; i < 4; i++) {
        int rowl = w * 4 + i;
        float4 a03 = *(float4*)(smc + (rowl * 260 + lane * 4) * 4);
        float4 a47 = *(float4*)(smc + (rowl * 260 + 128 + lane * 4) * 4);
        int node = n0 + rowl;
        float sp0 = a03.x * s0.x + a03.y * s0.y + a03.z * s0.z + a03.w * s0.w;
        float sp1 = a47.x * s1.x + a47.y * s1.y + a47.z * s1.z + a47.w * s1.w;
        float dp0 = a03.x * d0.x + a03.y * d0.y + a03.z * d0.z + a03.w * d0.w;
        float dp1 = a47.x * d1.x + a47.y * d1.y + a47.z * d1.z + a47.w * d1.w;
#pragma unroll
        for (int off = 16; off; off >>= 1) {
            sp0 += __shfl_xor_sync(0xffffffffu, sp0, off);
            sp1 += __shfl_xor_sync(0xffffffffu, sp1, off);
            dp0 += __shfl_xor_sync(0xffffffffu, dp0, off);
            dp1 += __shfl_xor_sync(0xffffffffu, dp1, off);
        }
        if (node < NN) {
            g_xwh[(size_t)node * 64 + lane]      = make_uint2(pack_h2(a03.x, a03.y),
                                                              pack_h2(a03.z, a03.w));
            g_xwh[(size_t)node * 64 + 32 + lane] = make_uint2(pack_h2(a47.x, a47.y),
                                                              pack_h2(a47.z, a47.w));
            if (lane == 0) {
                g_as[2 * node]     = sp0;
                g_as[2 * node + 1] = sp1;
                g_ad[2 * node]     = dp0;
                g_ad[2 * node + 1] = dp1;
            }
        }
    }
}

// scan stage 2+3 fused
__global__ void k_scanB() {
    __shared__ int sb[256];
    __shared__ int sp[256];
    int t = threadIdx.x;
    int b = blockIdx.x;

    sb[t] = (t < NB_SCAN) ? g_bsum[t] : 0;
    __syncthreads();
    for (int off = 1; off < 256; off <<= 1) {
        int u = (t >= off) ? sb[t - off] : 0;
        __syncthreads();
        sb[t] += u;
        __syncthreads();
    }
    int base = (b == 0) ? 0 : sb[b - 1];

    int i = b * 256 + t;
    int v = (i < NN) ? g_deg[i] : 0;
    sp[t] = v;
    __syncthreads();
    for (int off = 1; off < 256; off <<= 1) {
        int u = (t >= off) ? sp[t - off] : 0;
        __syncthreads();
        sp[t] += u;
        __syncthreads();
    }
    int excl = sp[t] - v + base;
    if (i < NN) { g_off[i] = excl; g_woff[i] = excl; }
}

// scatter: sources grouped by target
__global__ void k_scatter(const int* __restrict__ ei) {
    int e = blockIdx.x * blockDim.x + threadIdx.x;
    if (e >= TOTE) return;
    int s, t;
    if (e < EE) { s = ei[e]; t = ei[EE + e]; }
    else        { s = t = e - EE; }
    if ((unsigned)t >= NN || (unsigned)s >= NN) return;
    int pos = atomicAdd(&g_woff[t], 1);
    if ((unsigned)pos < TOTE) g_srcs[pos] = s;
}

// fused node kernel, 2 warps per node (one per head). lane owns 4 cols (8B half2x2).
__global__ void k_node(const float* __restrict__ bias, const float* __restrict__ fcw,
                       const float* __restrict__ fcb) {
    __shared__ float zpart[8][3];
    int tid  = threadIdx.x;
    int lane = tid & 31;
    int winb = tid >> 5;
    int gw   = blockIdx.x * 8 + winb;
    int n    = gw >> 1;
    int h    = gw & 1;

    int off = g_off[n], deg = g_deg[n];
    float adh = g_ad[2 * n + h];
    const uint2* xwb = g_xwh + h * 32 + lane;

    float4 acc = make_float4(0.f, 0.f, 0.f, 0.f);
    float den = 0.f;

    if (deg <= 32) {
        int s = 0; float l = -INFINITY;
        if (lane < deg) {
            s = g_srcs[off + lane];
            l = g_as[2 * s + h] + adh;
            l = l > 0.f ? l : 0.2f * l;
        }
        float m = l;
#pragma unroll
        for (int o = 16; o; o >>= 1)
            m = fmaxf(m, __shfl_xor_sync(0xffffffffu, m, o));
        float ex = (lane < deg) ? expf(l - m) : 0.f;
        den = ex;
#pragma unroll
        for (int o = 16; o; o >>= 1)
            den += __shfl_xor_sync(0xffffffffu, den, o);

        for (int j = 0; j < deg; j += 8) {
            int jj[8], ss[8];
            uint2 u[8];
            float e[8];
#pragma unroll
            for (int q = 0; q < 8; q++) jj[q] = min(j + q, deg - 1);
#pragma unroll
            for (int q = 0; q < 8; q++) ss[q] = __shfl_sync(0xffffffffu, s, jj[q]);
#pragma unroll
            for (int q = 0; q < 8; q++) u[q] = xwb[(size_t)ss[q] * 64];
#pragma unroll
            for (int q = 0; q < 8; q++)
                e[q] = (j + q < deg) ? __shfl_sync(0xffffffffu, ex, jj[q]) : 0.f;
#pragma unroll
            for (int q = 0; q < 8; q++) {
                float2 fa = __half22float2(*reinterpret_cast<__half2*>(&u[q].x));
                float2 fb = __half22float2(*reinterpret_cast<__half2*>(&u[q].y));
                acc.x += e[q] * fa.x; acc.y += e[q] * fa.y;
                acc.z += e[q] * fb.x; acc.w += e[q] * fb.y;
            }
        }
    } else {
        // slow path: two-pass (rare)
        float mas = -INFINITY;
        for (int i = lane; i < deg; i += 32)
            mas = fmaxf(mas, g_as[2 * g_srcs[off + i] + h]);
#pragma unroll
        for (int o = 16; o; o >>= 1)
            mas = fmaxf(mas, __shfl_xor_sync(0xffffffffu, mas, o));
        float m = mas + adh; m = m > 0.f ? m : 0.2f * m;

        for (int i0 = 0; i0 < deg; i0 += 32) {
            int cnt = min(32, deg - i0);
            int s = 0; float ex = 0.f;
            if (lane < cnt) {
                s = g_srcs[off + i0 + lane];
                float l = g_as[2 * s + h] + adh; l = l > 0.f ? l : 0.2f * l;
                ex = expf(l - m);
            }
            den += ex;
            for (int j = 0; j < cnt; j += 4) {
                int j1 = min(j + 1, cnt - 1), j2 = min(j + 2, cnt - 1), j3 = min(j + 3, cnt - 1);
                int s0 = __shfl_sync(0xffffffffu, s, j);
                int s1 = __shfl_sync(0xffffffffu, s, j1);
                int s2 = __shfl_sync(0xffffffffu, s, j2);
                int s3 = __shfl_sync(0xffffffffu, s, j3);
                uint2 u0 = xwb[(size_t)s0 * 64];
                uint2 u1 = xwb[(size_t)s1 * 64];
                uint2 u2 = xwb[(size_t)s2 * 64];
                uint2 u3 = xwb[(size_t)s3 * 64];
                float e0 = __shfl_sync(0xffffffffu, ex, j);
                float e1 = (j + 1 < cnt) ? __shfl_sync(0xffffffffu, ex, j1) : 0.f;
                float e2 = (j + 2 < cnt) ? __shfl_sync(0xffffffffu, ex, j2) : 0.f;
                float e3 = (j + 3 < cnt) ? __shfl_sync(0xffffffffu, ex, j3) : 0.f;
                float2 fa, fb;
                fa = __half22float2(*reinterpret_cast<__half2*>(&u0.x));
                fb = __half22float2(*reinterpret_cast<__half2*>(&u0.y));
                acc.x += e0 * fa.x; acc.y += e0 * fa.y; acc.z += e0 * fb.x; acc.w += e0 * fb.y;
                fa = __half22float2(*reinterpret_cast<__half2*>(&u1.x));
                fb = __half22float2(*reinterpret_cast<__half2*>(&u1.y));
                acc.x += e1 * fa.x; acc.y += e1 * fa.y; acc.z += e1 * fb.x; acc.w += e1 * fb.y;
                fa = __half22float2(*reinterpret_cast<__half2*>(&u2.x));
                fb = __half22float2(*reinterpret_cast<__half2*>(&u2.y));
                acc.x += e2 * fa.x; acc.y += e2 * fa.y; acc.z += e2 * fb.x; acc.w += e2 * fb.y;
                fa = __half22float2(*reinterpret_cast<__half2*>(&u3.x));
                fb = __half22float2(*reinterpret_cast<__half2*>(&u3.y));
                acc.x += e3 * fa.x; acc.y += e3 * fa.y; acc.z += e3 * fb.x; acc.w += e3 * fb.y;
            }
        }
#pragma unroll
        for (int o = 16; o; o >>= 1)
            den += __shfl_xor_sync(0xffffffffu, den, o);
    }
    float inv = 1.f / den;

    int cb = h * 128 + lane * 4;
    float4 b4 = *(const float4*)&bias[cb];
    float vv[4] = {acc.x * inv + b4.x, acc.y * inv + b4.y,
                   acc.z * inv + b4.z, acc.w * inv + b4.w};
    float z0 = 0.f, z1 = 0.f, z2 = 0.f;
#pragma unroll
    for (int mth = 0; mth < 4; mth++) {
        float val = vv[mth] > 0.f ? vv[mth] : 0.f;
        int k = cb + mth;
        z0 += val * fcw[k * 3 + 0];
        z1 += val * fcw[k * 3 + 1];
        z2 += val * fcw[k * 3 + 2];
    }
#pragma unroll
    for (int o = 16; o; o >>= 1) {
        z0 += __shfl_xor_sync(0xffffffffu, z0, o);
        z1 += __shfl_xor_sync(0xffffffffu, z1, o);
        z2 += __shfl_xor_sync(0xffffffffu, z2, o);
    }
    if (lane == 0) { zpart[winb][0] = z0; zpart[winb][1] = z1; zpart[winb][2] = z2; }
    __syncthreads();
    if (h == 0 && lane == 0) {
        float p0 = zpart[winb][0] + zpart[winb + 1][0] + fcb[0];
        float p1 = zpart[winb][1] + zpart[winb + 1][1] + fcb[1];
        float p2 = zpart[winb][2] + zpart[winb + 1][2] + fcb[2];
        float mx = fmaxf(p0, fmaxf(p1, p2));
        float ls = mx + logf(expf(p0 - mx) + expf(p1 - mx) + expf(p2 - mx));
        g_z[n * 3 + 0] = p0 - ls;
        g_z[n * 3 + 1] = p1 - ls;
        g_z[n * 3 + 2] = p2 - ls;
    }
}

// deterministic pool: batch sorted -> contiguous node range per graph.
__global__ void k_pool(const int* __restrict__ batch, const float* __restrict__ a,
                       float* __restrict__ out) {
    __shared__ float sz[3][256];
    int g = blockIdx.x;
    int t = threadIdx.x;
    int lo = 0, hi = NN;
    while (lo < hi) { int mid = (lo + hi) >> 1; if (batch[mid] < g) lo = mid + 1; else hi = mid; }
    int s0 = lo;
    hi = NN;
    while (lo < hi) { int mid = (lo + hi) >> 1; if (batch[mid] < g + 1) lo = mid + 1; else hi = mid; }
    int e0 = lo;

    float z0 = 0.f, z1 = 0.f, z2 = 0.f;
    for (int n = s0 + t; n < e0; n += 256) {
        z0 += g_z[n * 3 + 0];
        z1 += g_z[n * 3 + 1];
        z2 += g_z[n * 3 + 2];
    }
    sz[0][t] = z0; sz[1][t] = z1; sz[2][t] = z2;
    __syncthreads();
    for (int off = 128; off; off >>= 1) {
        if (t < off) {
            sz[0][t] += sz[0][t + off];
            sz[1][t] += sz[1][t + off];
            sz[2][t] += sz[2][t + off];
        }
        __syncthreads();
    }
    if (t == 0) {
        float sc = *a;
        float p0 = sc * sz[0][0], p1 = sc * sz[1][0], p2 = sc * sz[2][0];
        float mx = fmaxf(p0, fmaxf(p1, p2));
        float ls = mx + logf(expf(p0 - mx) + expf(p1 - mx) + expf(p2 - mx));
        out[g * 3 + 0] = p0 - ls;
        out[g * 3 + 1] = p1 - ls;
        out[g * 3 + 2] = p2 - ls;
    }
}

// ---------------- launch -----------------------------------------------------
extern "C" void kernel_launch(void* const* d_in, const int* in_sizes, int n_in,
                              void* d_out, int out_size) {
    const float* x     = (const float*)d_in[0];
    const int*   ei    = (const int*)d_in[1];
    const int*   batch = (const int*)d_in[2];
    const float* W     = (const float*)d_in[3];
    const float* att_s = (const float*)d_in[4];
    const float* att_d = (const float*)d_in[5];
    const float* bias  = (const float*)d_in[6];
    const float* fcw   = (const float*)d_in[7];
    const float* fcb   = (const float*)d_in[8];
    const float* a     = (const float*)d_in[9];
    float* out = (float*)d_out;

    static cudaStream_t s2 = 0;
    static cudaEvent_t evA = 0, evB = 0;
    if (s2 == 0) {
        cudaStreamCreateWithFlags(&s2, cudaStreamNonBlocking);
        cudaEventCreateWithFlags(&evA, cudaEventDisableTiming);
        cudaEventCreateWithFlags(&evB, cudaEventDisableTiming);
        cudaFuncSetAttribute(k_gemm, cudaFuncAttributeMaxDynamicSharedMemorySize, GSM);
    }

    // main: init -> wprep -> gemm ; side stream: CSR chain. gemm = 4th launch.
    k_init   <<<(NN + 255) / 256, 256>>>();
    cudaEventRecord(evA, 0);
    k_wprep  <<<32, 256>>>(W);
    cudaStreamWaitEvent(s2, evA, 0);
    k_deg    <<<(TOTE + 255) / 256, 256, 0, s2>>>(ei);
    k_gemm   <<<(NN + 31) / 32, 256, GSM>>>(x, att_s, att_d);   // 4th submission: profiled
    k_scan1  <<<NB_SCAN, 256, 0, s2>>>();
    k_scanB  <<<NB_SCAN, 256, 0, s2>>>();
    k_scatter<<<(TOTE + 255) / 256, 256, 0, s2>>>(ei);
    cudaEventRecord(evB, s2);
    cudaStreamWaitEvent(0, evB, 0);
    k_node   <<<(NN * 2) / 8, 256>>>(bias, fcw, fcb);
    k_pool   <<<GG, 256>>>(batch, a, out);
}